// round 3
// baseline (speedup 1.0000x reference)
#include <cuda_runtime.h>
#include <cstdint>

#define NPT 8192          // points per side
#define DIM 256           // feature dim
#define LOG2E  1.4426950408889634f
#define LN2    0.6931471805599453f
#define LOGN   9.0109133472f          // log(8192)
#define KS     (1.4426950408889634f / 64.0f)   // (q/128)*2*log2e : dequant*log2e fused
#define PIN_ROWS 6144                 // first 96MB of C pinned in L2 (evict_last)
#define NEG_INF (-__int_as_float(0x7f800000))

// ---------------- device scratch ----------------
__device__ short  gC [(size_t)NPT * NPT];   // q = round(128 * x_i . y_j), row-major in i
__device__ float  gA[NPT], gB[NPT];         // squared norms
__device__ float  gU[NPT], gV[NPT], gS[NPT];
__device__ float  gPM[64 * NPT], gPS[64 * NPT];  // column-LSE partials (64 i-blocks)

// ---------------- helpers ----------------
__device__ __forceinline__ float ex2(float x) {
    float r; asm("ex2.approx.ftz.f32 %0, %1;" : "=f"(r) : "f"(x)); return r;
}

// 256-bit loads with L2 eviction-priority hints (16 int16 values)
__device__ __forceinline__ void ld256_pin(const uint32_t* p, uint32_t* r) {
    asm volatile("ld.global.L2::evict_last.v8.b32 {%0,%1,%2,%3,%4,%5,%6,%7}, [%8];"
                 : "=r"(r[0]), "=r"(r[1]), "=r"(r[2]), "=r"(r[3]),
                   "=r"(r[4]), "=r"(r[5]), "=r"(r[6]), "=r"(r[7])
                 : "l"(p));
}
__device__ __forceinline__ void ld256_stream(const uint32_t* p, uint32_t* r) {
    asm volatile("ld.global.L2::evict_first.v8.b32 {%0,%1,%2,%3,%4,%5,%6,%7}, [%8];"
                 : "=r"(r[0]), "=r"(r[1]), "=r"(r[2]), "=r"(r[3]),
                   "=r"(r[4]), "=r"(r[5]), "=r"(r[6]), "=r"(r[7])
                 : "l"(p));
}

// branchless online log-sum-exp update (base-2 domain), exactly one EX2
#define BUPD(m, s, z) do {                        \
    float _d = (z) - (m);                         \
    float _e = ex2(0.0f - fabsf(_d));             \
    bool  _p = _d > 0.0f;                         \
    float _fa = _p ? _e : 1.0f;                   \
    float _fb = _p ? 1.0f : _e;                   \
    (s) = fmaf((s), _fa, _fb);                    \
    (m) = fmaxf((m), (z));                        \
} while (0)

// unpack one 32-bit word into two floats (low short, high short)
#define UNPK(w, flo, fhi) do {                    \
    flo = (float)((short)((w) & 0xffffu));        \
    fhi = (float)((short)((w) >> 16));            \
} while (0)

// ---------------- squared norms ----------------
__global__ __launch_bounds__(256) void norms_kernel(const float* __restrict__ X, int which) {
    int warp = threadIdx.x >> 5, lane = threadIdx.x & 31;
    int row  = blockIdx.x * 8 + warp;
    const float4* xp = (const float4*)(X + (size_t)row * DIM);
    float ss = 0.0f;
    #pragma unroll
    for (int c = lane; c < DIM / 4; c += 32) {
        float4 t = xp[c];
        ss += t.x * t.x + t.y * t.y + t.z * t.z + t.w * t.w;
    }
    #pragma unroll
    for (int off = 16; off; off >>= 1)
        ss += __shfl_xor_sync(0xffffffffu, ss, off);
    if (lane == 0) { if (which) gB[row] = ss; else gA[row] = ss; }
}

__global__ void init_kernel() {
    int j = blockIdx.x * 256 + threadIdx.x;
    gV[j] = -gB[j];
    gU[j] = -gA[j];
}

// ---------------- GEMM: q = round(128 * X Y^T), writes C only ----------------
#define BM 128
#define BN 128
#define BK 16

__device__ __forceinline__ unsigned pack2(int a, int b) {
    return (unsigned)(unsigned short)(short)a | ((unsigned)(unsigned short)(short)b << 16);
}

__global__ __launch_bounds__(256) void gemm_q_kernel(const float* __restrict__ X,
                                                     const float* __restrict__ Y) {
    __shared__ float As[BK][BM + 4];
    __shared__ float Bs[BK][BN + 4];
    int tid = threadIdx.x;
    int tx = tid & 15, ty = tid >> 4;
    int bi = blockIdx.y * BM, bj = blockIdx.x * BN;

    float acc[8][8];
    #pragma unroll
    for (int r = 0; r < 8; ++r)
        #pragma unroll
        for (int c = 0; c < 8; ++c) acc[r][c] = 0.0f;

    for (int k0 = 0; k0 < DIM; k0 += BK) {
        #pragma unroll
        for (int q = 0; q < 2; ++q) {
            int idx = tid + q * 256;        // 0..511
            int row = idx >> 2;             // 0..127
            int kf  = (idx & 3) << 2;       // 0,4,8,12
            float4 av = *(const float4*)&X[(size_t)(bi + row) * DIM + k0 + kf];
            As[kf + 0][row] = av.x; As[kf + 1][row] = av.y;
            As[kf + 2][row] = av.z; As[kf + 3][row] = av.w;
            float4 bv = *(const float4*)&Y[(size_t)(bj + row) * DIM + k0 + kf];
            Bs[kf + 0][row] = bv.x; Bs[kf + 1][row] = bv.y;
            Bs[kf + 2][row] = bv.z; Bs[kf + 3][row] = bv.w;
        }
        __syncthreads();
        #pragma unroll
        for (int kk = 0; kk < BK; ++kk) {
            float ra[8], rb[8];
            *(float4*)&ra[0] = *(const float4*)&As[kk][ty * 8];
            *(float4*)&ra[4] = *(const float4*)&As[kk][ty * 8 + 4];
            *(float4*)&rb[0] = *(const float4*)&Bs[kk][tx * 8];
            *(float4*)&rb[4] = *(const float4*)&Bs[kk][tx * 8 + 4];
            #pragma unroll
            for (int r = 0; r < 8; ++r)
                #pragma unroll
                for (int c = 0; c < 8; ++c)
                    acc[r][c] = fmaf(ra[r], rb[c], acc[r][c]);
        }
        __syncthreads();
    }

    int row_i = bi + ty * 8, col_j = bj + tx * 8;
    #pragma unroll
    for (int r = 0; r < 8; ++r) {
        int q0[8];
        #pragma unroll
        for (int c = 0; c < 8; ++c) {
            int qi = __float2int_rn(acc[r][c] * 128.0f);
            q0[c] = max(-32767, min(32767, qi));
        }
        uint4 pk;
        pk.x = pack2(q0[0], q0[1]); pk.y = pack2(q0[2], q0[3]);
        pk.z = pack2(q0[4], q0[5]); pk.w = pack2(q0[6], q0[7]);
        *(uint4*)&gC[(size_t)(row_i + r) * NPT + col_j] = pk;
    }
}

// ---------------- row logsumexp (u-update / final S) ----------------
// out[i] = LOGN - ln2 * log2( sum_j 2^( v_j*log2e + q[i][j]*KS ) )
// mode 0: out=gU ;  mode 1: out=gS
#define ROWS_PER_CTA 8

#define ROWBODY(LDFN)                                               \
    _Pragma("unroll 2")                                             \
    for (int c = 0; c < 16; ++c) {                                  \
        int idx = c * 32 + lane;           /* 32-byte units */      \
        uint32_t rw[8];                                             \
        LDFN(rowp + (size_t)idx * 8, rw);                           \
        const float4* wv = (const float4*)(w2 + (size_t)idx * 16);  \
        float4 w0 = wv[0], w1 = wv[1], w2r = wv[2], w3 = wv[3];     \
        float f0, f1;                                               \
        UNPK(rw[0], f0, f1);                                        \
        BUPD(m0, s0, fmaf(f0, KS, w0.x)); BUPD(m1, s1, fmaf(f1, KS, w0.y)); \
        UNPK(rw[1], f0, f1);                                        \
        BUPD(m2, s2, fmaf(f0, KS, w0.z)); BUPD(m3, s3, fmaf(f1, KS, w0.w)); \
        UNPK(rw[2], f0, f1);                                        \
        BUPD(m0, s0, fmaf(f0, KS, w1.x)); BUPD(m1, s1, fmaf(f1, KS, w1.y)); \
        UNPK(rw[3], f0, f1);                                        \
        BUPD(m2, s2, fmaf(f0, KS, w1.z)); BUPD(m3, s3, fmaf(f1, KS, w1.w)); \
        UNPK(rw[4], f0, f1);                                        \
        BUPD(m0, s0, fmaf(f0, KS, w2r.x)); BUPD(m1, s1, fmaf(f1, KS, w2r.y)); \
        UNPK(rw[5], f0, f1);                                        \
        BUPD(m2, s2, fmaf(f0, KS, w2r.z)); BUPD(m3, s3, fmaf(f1, KS, w2r.w)); \
        UNPK(rw[6], f0, f1);                                        \
        BUPD(m0, s0, fmaf(f0, KS, w3.x)); BUPD(m1, s1, fmaf(f1, KS, w3.y)); \
        UNPK(rw[7], f0, f1);                                        \
        BUPD(m2, s2, fmaf(f0, KS, w3.z)); BUPD(m3, s3, fmaf(f1, KS, w3.w)); \
    }

__global__ __launch_bounds__(256) void row_lse_kernel(int mode) {
    __shared__ float w2[NPT];
    float* __restrict__ out = mode ? gS : gU;

    int tid = threadIdx.x;
    const float4* w4 = (const float4*)gV;
    for (int idx = tid; idx < NPT / 4; idx += 256) {
        float4 t = w4[idx];
        t.x *= LOG2E; t.y *= LOG2E; t.z *= LOG2E; t.w *= LOG2E;
        ((float4*)w2)[idx] = t;
    }
    __syncthreads();

    int warp = tid >> 5, lane = tid & 31;
    int i = blockIdx.x * ROWS_PER_CTA + warp;
    const uint32_t* rowp = (const uint32_t*)(gC + (size_t)i * NPT);

    float m0 = NEG_INF, s0 = 0.0f, m1 = NEG_INF, s1 = 0.0f;
    float m2 = NEG_INF, s2 = 0.0f, m3 = NEG_INF, s3 = 0.0f;

    if (i < PIN_ROWS) { ROWBODY(ld256_pin) }
    else              { ROWBODY(ld256_stream) }

    // merge the four per-lane accumulators
    float ma = fmaxf(m0, m1);
    float sa = s0 * ex2(m0 - ma) + s1 * ex2(m1 - ma);
    float mb = fmaxf(m2, m3);
    float sb = s2 * ex2(m2 - mb) + s3 * ex2(m3 - mb);
    float m = fmaxf(ma, mb);
    float s = sa * ex2(ma - m) + sb * ex2(mb - m);
    // warp reduction of (m, s)
    #pragma unroll
    for (int off = 16; off; off >>= 1) {
        float mo = __shfl_xor_sync(0xffffffffu, m, off);
        float so = __shfl_xor_sync(0xffffffffu, s, off);
        float mn = fmaxf(m, mo);
        s = s * ex2(m - mn) + so * ex2(mo - mn);
        m = mn;
    }
    if (lane == 0) out[i] = LOGN - LN2 * (m + log2f(s));
}

// ---------------- column logsumexp (v-update), split over i ----------------
// grid (2 jblocks, 64 iblocks); CTA: 256 threads x 16 columns, 128 rows of i
#define IB_ROWS 128

#define COLBODY(LDFN)                                               \
    _Pragma("unroll 2")                                             \
    for (int ii = 0; ii < IB_ROWS; ++ii) {                          \
        uint32_t rw[8];                                             \
        LDFN(Cp + (size_t)ii * (NPT / 2), rw);                      \
        float u = su[ii];                                           \
        float f0, f1;                                               \
        UNPK(rw[0], f0, f1);                                        \
        BUPD(m[0], s[0], fmaf(f0, KS, u)); BUPD(m[1], s[1], fmaf(f1, KS, u)); \
        UNPK(rw[1], f0, f1);                                        \
        BUPD(m[2], s[2], fmaf(f0, KS, u)); BUPD(m[3], s[3], fmaf(f1, KS, u)); \
        UNPK(rw[2], f0, f1);                                        \
        BUPD(m[4], s[4], fmaf(f0, KS, u)); BUPD(m[5], s[5], fmaf(f1, KS, u)); \
        UNPK(rw[3], f0, f1);                                        \
        BUPD(m[6], s[6], fmaf(f0, KS, u)); BUPD(m[7], s[7], fmaf(f1, KS, u)); \
        UNPK(rw[4], f0, f1);                                        \
        BUPD(m[8], s[8], fmaf(f0, KS, u)); BUPD(m[9], s[9], fmaf(f1, KS, u)); \
        UNPK(rw[5], f0, f1);                                        \
        BUPD(m[10], s[10], fmaf(f0, KS, u)); BUPD(m[11], s[11], fmaf(f1, KS, u)); \
        UNPK(rw[6], f0, f1);                                        \
        BUPD(m[12], s[12], fmaf(f0, KS, u)); BUPD(m[13], s[13], fmaf(f1, KS, u)); \
        UNPK(rw[7], f0, f1);                                        \
        BUPD(m[14], s[14], fmaf(f0, KS, u)); BUPD(m[15], s[15], fmaf(f1, KS, u)); \
    }

__global__ __launch_bounds__(256) void col_lse_kernel() {
    __shared__ float su[IB_ROWS];
    int tid = threadIdx.x;
    int jb = blockIdx.x, ib = blockIdx.y;
    int i0 = ib * IB_ROWS;

    if (tid < IB_ROWS) su[tid] = gU[i0 + tid] * LOG2E;
    __syncthreads();

    int j0 = jb * 4096 + tid * 16;   // column index (in shorts)
    const uint32_t* Cp = (const uint32_t*)(gC + (size_t)i0 * NPT + j0);

    float m[16], s[16];
    #pragma unroll
    for (int k = 0; k < 16; ++k) { m[k] = NEG_INF; s[k] = 0.0f; }

    if (i0 < PIN_ROWS) { COLBODY(ld256_pin) }
    else               { COLBODY(ld256_stream) }

    float* pm = &gPM[(size_t)ib * NPT + j0];
    float* ps = &gPS[(size_t)ib * NPT + j0];
    #pragma unroll
    for (int k = 0; k < 4; ++k) {
        *(float4*)&pm[k * 4] = make_float4(m[k*4+0], m[k*4+1], m[k*4+2], m[k*4+3]);
        *(float4*)&ps[k * 4] = make_float4(s[k*4+0], s[k*4+1], s[k*4+2], s[k*4+3]);
    }
}

__global__ __launch_bounds__(256) void col_combine_kernel() {
    int j = blockIdx.x * 256 + threadIdx.x;
    float m = NEG_INF, s = 0.0f;
    #pragma unroll 8
    for (int p = 0; p < 64; ++p) {
        float mp = gPM[(size_t)p * NPT + j];
        float sp = gPS[(size_t)p * NPT + j];
        float mn = fmaxf(m, mp);
        s = s * ex2(m - mn) + sp * ex2(mp - mn);
        m = mn;
    }
    gV[j] = LOGN - LN2 * (m + log2f(s));
}

// ---------------- final value reduction ----------------
// value = sum_i (a_i + u_i) * exp(u_i - LOGN - S_i) + (1/N) * sum_j (b_j + v_j)
__global__ __launch_bounds__(256) void final_kernel(float* __restrict__ out) {
    __shared__ float red[256];
    int tid = threadIdx.x;
    float acc = 0.0f;
    for (int i = tid; i < NPT; i += 256) {
        float fi = gA[i] + gU[i];
        float ri = expf(gU[i] - LOGN - gS[i]);
        float gj = gB[i] + gV[i];
        acc += fi * ri + gj * (1.0f / NPT);
    }
    red[tid] = acc;
    __syncthreads();
    #pragma unroll
    for (int st = 128; st; st >>= 1) {
        if (tid < st) red[tid] += red[tid + st];
        __syncthreads();
    }
    if (tid == 0) out[0] = sqrtf(red[0]);
}

// ---------------- launch ----------------
extern "C" void kernel_launch(void* const* d_in, const int* in_sizes, int n_in,
                              void* d_out, int out_size) {
    const float* X = (const float*)d_in[0];   // source [8192, 256]
    const float* Y = (const float*)d_in[1];   // target [8192, 256]
    float* out = (float*)d_out;

    norms_kernel<<<NPT / 8, 256>>>(X, 0);
    norms_kernel<<<NPT / 8, 256>>>(Y, 1);
    init_kernel<<<NPT / 256, 256>>>();

    dim3 gg(NPT / BN, NPT / BM);
    gemm_q_kernel<<<gg, 256>>>(X, Y);

    dim3 cg(2, 64);
    for (int it = 0; it < 50; ++it) {
        row_lse_kernel<<<NPT / ROWS_PER_CTA, 256>>>(0);  // u <- v  (rows of C)
        col_lse_kernel<<<cg, 256>>>();                    // v partials (cols of C)
        col_combine_kernel<<<NPT / 256, 256>>>();         // v <- combine
    }
    row_lse_kernel<<<NPT / ROWS_PER_CTA, 256>>>(1);      // S_i with final v
    final_kernel<<<1, 256>>>(out);
}

// round 5
// speedup vs baseline: 1.4724x; 1.4724x over previous
#include <cuda_runtime.h>
#include <cstdint>

#define NPT 8192          // points per side
#define DIM 256           // feature dim
#define LOG2E  1.4426950408889634f
#define LN2    0.6931471805599453f
#define LOGN   9.0109133472f          // log(8192)
#define KS     (1.4426950408889634f / 64.0f)   // (q/128)*2*log2e : dequant*log2e fused
#define NEG_INF (-__int_as_float(0x7f800000))

// ---------------- device scratch ----------------
__device__ short  gC [(size_t)NPT * NPT];   // q = round(128 * x_i . y_j), row-major in i
__device__ float  gA[NPT], gB[NPT];         // squared norms
__device__ float  gU[NPT], gV[NPT], gS[NPT];
__device__ float  gPM[128 * NPT], gPS[128 * NPT];  // column-LSE partials (128 i-blocks)

// ---------------- helpers ----------------
__device__ __forceinline__ float ex2(float x) {
    float r; asm("ex2.approx.ftz.f32 %0, %1;" : "=f"(r) : "f"(x)); return r;
}

// branchless online log-sum-exp update (base-2 domain), exactly one EX2
#define BUPD(m, s, z) do {                        \
    float _d = (z) - (m);                         \
    float _e = ex2(0.0f - fabsf(_d));             \
    bool  _p = _d > 0.0f;                         \
    float _fa = _p ? _e : 1.0f;                   \
    float _fb = _p ? 1.0f : _e;                   \
    (s) = fmaf((s), _fa, _fb);                    \
    (m) = fmaxf((m), (z));                        \
} while (0)

// unpack one 32-bit word into two floats (low short, high short)
#define UNPK(w, flo, fhi) do {                    \
    flo = (float)((short)((w) & 0xffffu));        \
    fhi = (float)((short)((w) >> 16));            \
} while (0)

// ---------------- squared norms ----------------
__global__ __launch_bounds__(256) void norms_kernel(const float* __restrict__ X, int which) {
    int warp = threadIdx.x >> 5, lane = threadIdx.x & 31;
    int row  = blockIdx.x * 8 + warp;
    const float4* xp = (const float4*)(X + (size_t)row * DIM);
    float ss = 0.0f;
    #pragma unroll
    for (int c = lane; c < DIM / 4; c += 32) {
        float4 t = xp[c];
        ss += t.x * t.x + t.y * t.y + t.z * t.z + t.w * t.w;
    }
    #pragma unroll
    for (int off = 16; off; off >>= 1)
        ss += __shfl_xor_sync(0xffffffffu, ss, off);
    if (lane == 0) { if (which) gB[row] = ss; else gA[row] = ss; }
}

__global__ void init_kernel() {
    int j = blockIdx.x * 256 + threadIdx.x;
    gV[j] = -gB[j];
    gU[j] = -gA[j];
}

// ---------------- GEMM: q = round(128 * X Y^T), writes C only ----------------
#define BM 128
#define BN 128
#define BK 16

__device__ __forceinline__ unsigned pack2(int a, int b) {
    return (unsigned)(unsigned short)(short)a | ((unsigned)(unsigned short)(short)b << 16);
}

__global__ __launch_bounds__(256) void gemm_q_kernel(const float* __restrict__ X,
                                                     const float* __restrict__ Y) {
    __shared__ float As[BK][BM + 4];
    __shared__ float Bs[BK][BN + 4];
    int tid = threadIdx.x;
    int tx = tid & 15, ty = tid >> 4;
    int bi = blockIdx.y * BM, bj = blockIdx.x * BN;

    float acc[8][8];
    #pragma unroll
    for (int r = 0; r < 8; ++r)
        #pragma unroll
        for (int c = 0; c < 8; ++c) acc[r][c] = 0.0f;

    for (int k0 = 0; k0 < DIM; k0 += BK) {
        #pragma unroll
        for (int q = 0; q < 2; ++q) {
            int idx = tid + q * 256;        // 0..511
            int row = idx >> 2;             // 0..127
            int kf  = (idx & 3) << 2;       // 0,4,8,12
            float4 av = *(const float4*)&X[(size_t)(bi + row) * DIM + k0 + kf];
            As[kf + 0][row] = av.x; As[kf + 1][row] = av.y;
            As[kf + 2][row] = av.z; As[kf + 3][row] = av.w;
            float4 bv = *(const float4*)&Y[(size_t)(bj + row) * DIM + k0 + kf];
            Bs[kf + 0][row] = bv.x; Bs[kf + 1][row] = bv.y;
            Bs[kf + 2][row] = bv.z; Bs[kf + 3][row] = bv.w;
        }
        __syncthreads();
        #pragma unroll
        for (int kk = 0; kk < BK; ++kk) {
            float ra[8], rb[8];
            *(float4*)&ra[0] = *(const float4*)&As[kk][ty * 8];
            *(float4*)&ra[4] = *(const float4*)&As[kk][ty * 8 + 4];
            *(float4*)&rb[0] = *(const float4*)&Bs[kk][tx * 8];
            *(float4*)&rb[4] = *(const float4*)&Bs[kk][tx * 8 + 4];
            #pragma unroll
            for (int r = 0; r < 8; ++r)
                #pragma unroll
                for (int c = 0; c < 8; ++c)
                    acc[r][c] = fmaf(ra[r], rb[c], acc[r][c]);
        }
        __syncthreads();
    }

    int row_i = bi + ty * 8, col_j = bj + tx * 8;
    #pragma unroll
    for (int r = 0; r < 8; ++r) {
        int q0[8];
        #pragma unroll
        for (int c = 0; c < 8; ++c) {
            int qi = __float2int_rn(acc[r][c] * 128.0f);
            q0[c] = max(-32767, min(32767, qi));
        }
        uint4 pk;
        pk.x = pack2(q0[0], q0[1]); pk.y = pack2(q0[2], q0[3]);
        pk.z = pack2(q0[4], q0[5]); pk.w = pack2(q0[6], q0[7]);
        *(uint4*)&gC[(size_t)(row_i + r) * NPT + col_j] = pk;
    }
}

// ---------------- row logsumexp (u-update / final S) ----------------
// out[i] = LOGN - ln2 * log2( sum_j 2^( v_j*log2e + q[i][j]*KS ) )
// mode 0: out=gU ;  mode 1: out=gS
#define ROWS_PER_CTA 8

__global__ __launch_bounds__(256) void row_lse_kernel(int mode) {
    __shared__ float w2[NPT];
    float* __restrict__ out = mode ? gS : gU;

    int tid = threadIdx.x;
    const float4* w4 = (const float4*)gV;
    for (int idx = tid; idx < NPT / 4; idx += 256) {
        float4 t = w4[idx];
        t.x *= LOG2E; t.y *= LOG2E; t.z *= LOG2E; t.w *= LOG2E;
        ((float4*)w2)[idx] = t;
    }
    __syncthreads();

    int warp = tid >> 5, lane = tid & 31;
    int i = blockIdx.x * ROWS_PER_CTA + warp;
    const uint4* __restrict__ rowp = (const uint4*)(gC + (size_t)i * NPT);

    float m0 = NEG_INF, s0 = 0.0f, m1 = NEG_INF, s1 = 0.0f;
    float m2 = NEG_INF, s2 = 0.0f, m3 = NEG_INF, s3 = 0.0f;

    #pragma unroll 4
    for (int c = 0; c < 32; ++c) {             // 32 iters x 8 shorts/lane
        int idx = c * 32 + lane;               // uint4 index (16B each)
        uint4 rw = rowp[idx];
        const float4* wv = (const float4*)(w2 + (size_t)idx * 8);
        float4 wa = wv[0], wb = wv[1];
        float f0, f1;
        UNPK(rw.x, f0, f1);
        BUPD(m0, s0, fmaf(f0, KS, wa.x)); BUPD(m1, s1, fmaf(f1, KS, wa.y));
        UNPK(rw.y, f0, f1);
        BUPD(m2, s2, fmaf(f0, KS, wa.z)); BUPD(m3, s3, fmaf(f1, KS, wa.w));
        UNPK(rw.z, f0, f1);
        BUPD(m0, s0, fmaf(f0, KS, wb.x)); BUPD(m1, s1, fmaf(f1, KS, wb.y));
        UNPK(rw.w, f0, f1);
        BUPD(m2, s2, fmaf(f0, KS, wb.z)); BUPD(m3, s3, fmaf(f1, KS, wb.w));
    }

    // merge the four per-lane accumulators
    float ma = fmaxf(m0, m1);
    float sa = s0 * ex2(m0 - ma) + s1 * ex2(m1 - ma);
    float mb = fmaxf(m2, m3);
    float sb = s2 * ex2(m2 - mb) + s3 * ex2(m3 - mb);
    float m = fmaxf(ma, mb);
    float s = sa * ex2(ma - m) + sb * ex2(mb - m);
    // warp reduction of (m, s)
    #pragma unroll
    for (int off = 16; off; off >>= 1) {
        float mo = __shfl_xor_sync(0xffffffffu, m, off);
        float so = __shfl_xor_sync(0xffffffffu, s, off);
        float mn = fmaxf(m, mo);
        s = s * ex2(m - mn) + so * ex2(mo - mn);
        m = mn;
    }
    if (lane == 0) out[i] = LOGN - LN2 * (m + log2f(s));
}

// ---------------- column logsumexp (v-update), split over i ----------------
// grid (4 jblocks, 128 iblocks); CTA: 256 threads x 8 columns, 64 rows of i
#define IB_ROWS 64

__global__ __launch_bounds__(256) void col_lse_kernel() {
    __shared__ float su[IB_ROWS];
    int tid = threadIdx.x;
    int jb = blockIdx.x, ib = blockIdx.y;
    int i0 = ib * IB_ROWS;

    if (tid < IB_ROWS) su[tid] = gU[i0 + tid] * LOG2E;
    __syncthreads();

    int j0 = jb * 2048 + tid * 8;   // column index (in shorts)
    const uint4* __restrict__ Cp = (const uint4*)(gC + (size_t)i0 * NPT + j0);

    float m[8], s[8];
    #pragma unroll
    for (int k = 0; k < 8; ++k) { m[k] = NEG_INF; s[k] = 0.0f; }

    #pragma unroll 4
    for (int ii = 0; ii < IB_ROWS; ++ii) {
        uint4 rw = Cp[(size_t)ii * (NPT / 8)];
        float u = su[ii];
        float f0, f1;
        UNPK(rw.x, f0, f1);
        BUPD(m[0], s[0], fmaf(f0, KS, u)); BUPD(m[1], s[1], fmaf(f1, KS, u));
        UNPK(rw.y, f0, f1);
        BUPD(m[2], s[2], fmaf(f0, KS, u)); BUPD(m[3], s[3], fmaf(f1, KS, u));
        UNPK(rw.z, f0, f1);
        BUPD(m[4], s[4], fmaf(f0, KS, u)); BUPD(m[5], s[5], fmaf(f1, KS, u));
        UNPK(rw.w, f0, f1);
        BUPD(m[6], s[6], fmaf(f0, KS, u)); BUPD(m[7], s[7], fmaf(f1, KS, u));
    }

    float* pm = &gPM[(size_t)ib * NPT + j0];
    float* ps = &gPS[(size_t)ib * NPT + j0];
    #pragma unroll
    for (int k = 0; k < 2; ++k) {
        *(float4*)&pm[k * 4] = make_float4(m[k*4+0], m[k*4+1], m[k*4+2], m[k*4+3]);
        *(float4*)&ps[k * 4] = make_float4(s[k*4+0], s[k*4+1], s[k*4+2], s[k*4+3]);
    }
}

__global__ __launch_bounds__(256) void col_combine_kernel() {
    int j = blockIdx.x * 256 + threadIdx.x;
    float m = NEG_INF, s = 0.0f;
    #pragma unroll 8
    for (int p = 0; p < 128; ++p) {
        float mp = gPM[(size_t)p * NPT + j];
        float sp = gPS[(size_t)p * NPT + j];
        float mn = fmaxf(m, mp);
        s = s * ex2(m - mn) + sp * ex2(mp - mn);
        m = mn;
    }
    gV[j] = LOGN - LN2 * (m + log2f(s));
}

// ---------------- final value reduction ----------------
// value = sum_i (a_i + u_i) * exp(u_i - LOGN - S_i) + (1/N) * sum_j (b_j + v_j)
__global__ __launch_bounds__(256) void final_kernel(float* __restrict__ out) {
    __shared__ float red[256];
    int tid = threadIdx.x;
    float acc = 0.0f;
    for (int i = tid; i < NPT; i += 256) {
        float fi = gA[i] + gU[i];
        float ri = expf(gU[i] - LOGN - gS[i]);
        float gj = gB[i] + gV[i];
        acc += fi * ri + gj * (1.0f / NPT);
    }
    red[tid] = acc;
    __syncthreads();
    #pragma unroll
    for (int st = 128; st; st >>= 1) {
        if (tid < st) red[tid] += red[tid + st];
        __syncthreads();
    }
    if (tid == 0) out[0] = sqrtf(red[0]);
}

// ---------------- launch ----------------
extern "C" void kernel_launch(void* const* d_in, const int* in_sizes, int n_in,
                              void* d_out, int out_size) {
    const float* X = (const float*)d_in[0];   // source [8192, 256]
    const float* Y = (const float*)d_in[1];   // target [8192, 256]
    float* out = (float*)d_out;

    norms_kernel<<<NPT / 8, 256>>>(X, 0);
    norms_kernel<<<NPT / 8, 256>>>(Y, 1);
    init_kernel<<<NPT / 256, 256>>>();

    dim3 gg(NPT / BN, NPT / BM);
    gemm_q_kernel<<<gg, 256>>>(X, Y);

    dim3 cg(4, 128);
    for (int it = 0; it < 50; ++it) {
        row_lse_kernel<<<NPT / ROWS_PER_CTA, 256>>>(0);  // u <- v  (rows of C)
        col_lse_kernel<<<cg, 256>>>();                    // v partials (cols of C)
        col_combine_kernel<<<NPT / 256, 256>>>();         // v <- combine
    }
    row_lse_kernel<<<NPT / ROWS_PER_CTA, 256>>>(1);      // S_i with final v
    final_kernel<<<1, 256>>>(out);
}

// round 6
// speedup vs baseline: 1.7263x; 1.1724x over previous
#include <cuda_runtime.h>
#include <cstdint>

#define NPT 8192          // points per side
#define DIM 256           // feature dim
#define LOG2E  1.4426950408889634f
#define LN2    0.6931471805599453f
#define LOGN   9.0109133472f          // log(8192)
#define KS     (1.4426950408889634f / 64.0f)   // (q/128)*2*log2e : dequant*log2e fused
#define MAGB   0x4B000000u            // 2^23 magic base
#define MAGF   8421376.0f             // 2^23 + 32768 (exact in f32)
#define NEG_INF (-__int_as_float(0x7f800000))

// ---------------- device scratch ----------------
__device__ unsigned short gC [(size_t)NPT * NPT]; // u16 = round(128*x.y) + 32768
__device__ float  gA[NPT], gB[NPT];               // squared norms
__device__ float  gU[NPT], gV[NPT], gS[NPT];
__device__ float  gPM[128 * NPT], gPS[128 * NPT]; // column-LSE partials (128 i-blocks)

// ---------------- helpers ----------------
__device__ __forceinline__ float ex2(float x) {
    float r; asm("ex2.approx.ftz.f32 %0, %1;" : "=f"(r) : "f"(x)); return r;
}

// branchless online log-sum-exp update (base-2 domain), exactly one EX2
#define BUPD(m, s, z) do {                        \
    float _d = (z) - (m);                         \
    float _e = ex2(0.0f - fabsf(_d));             \
    bool  _p = _d > 0.0f;                         \
    float _fa = _p ? _e : 1.0f;                   \
    float _fb = _p ? 1.0f : _e;                   \
    (s) = fmaf((s), _fa, _fb);                    \
    (m) = fmaxf((m), (z));                        \
} while (0)

// unpack one 32-bit word (two offset-binary u16) into two floats == q (exact).
// lo: LOP3 (mask+or), hi: PRMT; then exact FADD of -(2^23+32768). No I2F.
#define UNPK2(w, flo, fhi) do {                               \
    unsigned _lo = ((w) & 0x0000FFFFu) | MAGB;                \
    unsigned _hi = __byte_perm((w), MAGB, 0x7432);            \
    flo = __uint_as_float(_lo) - MAGF;                        \
    fhi = __uint_as_float(_hi) - MAGF;                        \
} while (0)

// ---------------- squared norms ----------------
__global__ __launch_bounds__(256) void norms_kernel(const float* __restrict__ X, int which) {
    int warp = threadIdx.x >> 5, lane = threadIdx.x & 31;
    int row  = blockIdx.x * 8 + warp;
    const float4* xp = (const float4*)(X + (size_t)row * DIM);
    float ss = 0.0f;
    #pragma unroll
    for (int c = lane; c < DIM / 4; c += 32) {
        float4 t = xp[c];
        ss += t.x * t.x + t.y * t.y + t.z * t.z + t.w * t.w;
    }
    #pragma unroll
    for (int off = 16; off; off >>= 1)
        ss += __shfl_xor_sync(0xffffffffu, ss, off);
    if (lane == 0) { if (which) gB[row] = ss; else gA[row] = ss; }
}

__global__ void init_kernel() {
    int j = blockIdx.x * 256 + threadIdx.x;
    gV[j] = -gB[j];
    gU[j] = -gA[j];
}

// ---------------- GEMM: u16 = round(128 * X Y^T) + 32768 ----------------
#define BM 128
#define BN 128
#define BK 16

__device__ __forceinline__ unsigned pack2(int a, int b) {
    return ((unsigned)a & 0xffffu) | (((unsigned)b & 0xffffu) << 16);
}

__global__ __launch_bounds__(256) void gemm_q_kernel(const float* __restrict__ X,
                                                     const float* __restrict__ Y) {
    __shared__ float As[BK][BM + 4];
    __shared__ float Bs[BK][BN + 4];
    int tid = threadIdx.x;
    int tx = tid & 15, ty = tid >> 4;
    int bi = blockIdx.y * BM, bj = blockIdx.x * BN;

    float acc[8][8];
    #pragma unroll
    for (int r = 0; r < 8; ++r)
        #pragma unroll
        for (int c = 0; c < 8; ++c) acc[r][c] = 0.0f;

    for (int k0 = 0; k0 < DIM; k0 += BK) {
        #pragma unroll
        for (int q = 0; q < 2; ++q) {
            int idx = tid + q * 256;        // 0..511
            int row = idx >> 2;             // 0..127
            int kf  = (idx & 3) << 2;       // 0,4,8,12
            float4 av = *(const float4*)&X[(size_t)(bi + row) * DIM + k0 + kf];
            As[kf + 0][row] = av.x; As[kf + 1][row] = av.y;
            As[kf + 2][row] = av.z; As[kf + 3][row] = av.w;
            float4 bv = *(const float4*)&Y[(size_t)(bj + row) * DIM + k0 + kf];
            Bs[kf + 0][row] = bv.x; Bs[kf + 1][row] = bv.y;
            Bs[kf + 2][row] = bv.z; Bs[kf + 3][row] = bv.w;
        }
        __syncthreads();
        #pragma unroll
        for (int kk = 0; kk < BK; ++kk) {
            float ra[8], rb[8];
            *(float4*)&ra[0] = *(const float4*)&As[kk][ty * 8];
            *(float4*)&ra[4] = *(const float4*)&As[kk][ty * 8 + 4];
            *(float4*)&rb[0] = *(const float4*)&Bs[kk][tx * 8];
            *(float4*)&rb[4] = *(const float4*)&Bs[kk][tx * 8 + 4];
            #pragma unroll
            for (int r = 0; r < 8; ++r)
                #pragma unroll
                for (int c = 0; c < 8; ++c)
                    acc[r][c] = fmaf(ra[r], rb[c], acc[r][c]);
        }
        __syncthreads();
    }

    int row_i = bi + ty * 8, col_j = bj + tx * 8;
    #pragma unroll
    for (int r = 0; r < 8; ++r) {
        int q0[8];
        #pragma unroll
        for (int c = 0; c < 8; ++c) {
            int qi = __float2int_rn(acc[r][c] * 128.0f);
            q0[c] = max(-32767, min(32767, qi)) + 32768;   // offset-binary
        }
        uint4 pk;
        pk.x = pack2(q0[0], q0[1]); pk.y = pack2(q0[2], q0[3]);
        pk.z = pack2(q0[4], q0[5]); pk.w = pack2(q0[6], q0[7]);
        *(uint4*)&gC[(size_t)(row_i + r) * NPT + col_j] = pk;
    }
}

// ---------------- row logsumexp (u-update / final S) ----------------
// out[i] = LOGN - ln2 * log2( sum_j 2^( v_j*log2e + q[i][j]*KS ) )
// mode 0: out=gU ;  mode 1: out=gS
#define ROWS_PER_CTA 8

__global__ __launch_bounds__(256) void row_lse_kernel(int mode) {
    __shared__ float w2[NPT];
    float* __restrict__ out = mode ? gS : gU;

    int tid = threadIdx.x;
    const float4* w4 = (const float4*)gV;
    for (int idx = tid; idx < NPT / 4; idx += 256) {
        float4 t = w4[idx];
        t.x *= LOG2E; t.y *= LOG2E; t.z *= LOG2E; t.w *= LOG2E;
        ((float4*)w2)[idx] = t;
    }
    __syncthreads();

    int warp = tid >> 5, lane = tid & 31;
    int i = blockIdx.x * ROWS_PER_CTA + warp;
    const uint4* __restrict__ rowp = (const uint4*)(gC + (size_t)i * NPT);

    float m0 = NEG_INF, s0 = 0.0f, m1 = NEG_INF, s1 = 0.0f;
    float m2 = NEG_INF, s2 = 0.0f, m3 = NEG_INF, s3 = 0.0f;

    #pragma unroll 4
    for (int c = 0; c < 32; ++c) {             // 32 iters x 8 shorts/lane
        int idx = c * 32 + lane;               // uint4 index (16B each)
        uint4 rw = __ldcs(rowp + idx);
        const float4* wv = (const float4*)(w2 + (size_t)idx * 8);
        float4 wa = wv[0], wb = wv[1];
        float f0, f1;
        UNPK2(rw.x, f0, f1);
        BUPD(m0, s0, fmaf(f0, KS, wa.x)); BUPD(m1, s1, fmaf(f1, KS, wa.y));
        UNPK2(rw.y, f0, f1);
        BUPD(m2, s2, fmaf(f0, KS, wa.z)); BUPD(m3, s3, fmaf(f1, KS, wa.w));
        UNPK2(rw.z, f0, f1);
        BUPD(m0, s0, fmaf(f0, KS, wb.x)); BUPD(m1, s1, fmaf(f1, KS, wb.y));
        UNPK2(rw.w, f0, f1);
        BUPD(m2, s2, fmaf(f0, KS, wb.z)); BUPD(m3, s3, fmaf(f1, KS, wb.w));
    }

    // merge the four per-lane accumulators
    float ma = fmaxf(m0, m1);
    float sa = s0 * ex2(m0 - ma) + s1 * ex2(m1 - ma);
    float mb = fmaxf(m2, m3);
    float sb = s2 * ex2(m2 - mb) + s3 * ex2(m3 - mb);
    float m = fmaxf(ma, mb);
    float s = sa * ex2(ma - m) + sb * ex2(mb - m);
    // warp reduction of (m, s)
    #pragma unroll
    for (int off = 16; off; off >>= 1) {
        float mo = __shfl_xor_sync(0xffffffffu, m, off);
        float so = __shfl_xor_sync(0xffffffffu, s, off);
        float mn = fmaxf(m, mo);
        s = s * ex2(m - mn) + so * ex2(mo - mn);
        m = mn;
    }
    if (lane == 0) out[i] = LOGN - LN2 * (m + log2f(s));
}

// ---------------- column logsumexp (v-update), split over i ----------------
// grid (4 jblocks, 128 iblocks); CTA: 256 threads x 8 columns, 64 rows of i
#define IB_ROWS 64

__global__ __launch_bounds__(256) void col_lse_kernel() {
    __shared__ float su[IB_ROWS];
    int tid = threadIdx.x;
    int jb = blockIdx.x, ib = blockIdx.y;
    int i0 = ib * IB_ROWS;

    if (tid < IB_ROWS) su[tid] = gU[i0 + tid] * LOG2E;
    __syncthreads();

    int j0 = jb * 2048 + tid * 8;   // column index (in shorts)
    const uint4* __restrict__ Cp = (const uint4*)(gC + (size_t)i0 * NPT + j0);

    float m[8], s[8];
    #pragma unroll
    for (int k = 0; k < 8; ++k) { m[k] = NEG_INF; s[k] = 0.0f; }

    #pragma unroll 4
    for (int ii = 0; ii < IB_ROWS; ++ii) {
        uint4 rw = __ldcs(Cp + (size_t)ii * (NPT / 8));
        float u = su[ii];
        float f0, f1;
        UNPK2(rw.x, f0, f1);
        BUPD(m[0], s[0], fmaf(f0, KS, u)); BUPD(m[1], s[1], fmaf(f1, KS, u));
        UNPK2(rw.y, f0, f1);
        BUPD(m[2], s[2], fmaf(f0, KS, u)); BUPD(m[3], s[3], fmaf(f1, KS, u));
        UNPK2(rw.z, f0, f1);
        BUPD(m[4], s[4], fmaf(f0, KS, u)); BUPD(m[5], s[5], fmaf(f1, KS, u));
        UNPK2(rw.w, f0, f1);
        BUPD(m[6], s[6], fmaf(f0, KS, u)); BUPD(m[7], s[7], fmaf(f1, KS, u));
    }

    float* pm = &gPM[(size_t)ib * NPT + j0];
    float* ps = &gPS[(size_t)ib * NPT + j0];
    #pragma unroll
    for (int k = 0; k < 2; ++k) {
        *(float4*)&pm[k * 4] = make_float4(m[k*4+0], m[k*4+1], m[k*4+2], m[k*4+3]);
        *(float4*)&ps[k * 4] = make_float4(s[k*4+0], s[k*4+1], s[k*4+2], s[k*4+3]);
    }
}

__global__ __launch_bounds__(256) void col_combine_kernel() {
    int j = blockIdx.x * 256 + threadIdx.x;
    float m = NEG_INF, s = 0.0f;
    #pragma unroll 8
    for (int p = 0; p < 128; ++p) {
        float mp = gPM[(size_t)p * NPT + j];
        float sp = gPS[(size_t)p * NPT + j];
        float mn = fmaxf(m, mp);
        s = s * ex2(m - mn) + sp * ex2(mp - mn);
        m = mn;
    }
    gV[j] = LOGN - LN2 * (m + log2f(s));
}

// ---------------- final value reduction ----------------
// value = sum_i (a_i + u_i) * exp(u_i - LOGN - S_i) + (1/N) * sum_j (b_j + v_j)
__global__ __launch_bounds__(256) void final_kernel(float* __restrict__ out) {
    __shared__ float red[256];
    int tid = threadIdx.x;
    float acc = 0.0f;
    for (int i = tid; i < NPT; i += 256) {
        float fi = gA[i] + gU[i];
        float ri = expf(gU[i] - LOGN - gS[i]);
        float gj = gB[i] + gV[i];
        acc += fi * ri + gj * (1.0f / NPT);
    }
    red[tid] = acc;
    __syncthreads();
    #pragma unroll
    for (int st = 128; st; st >>= 1) {
        if (tid < st) red[tid] += red[tid + st];
        __syncthreads();
    }
    if (tid == 0) out[0] = sqrtf(red[0]);
}

// ---------------- launch ----------------
extern "C" void kernel_launch(void* const* d_in, const int* in_sizes, int n_in,
                              void* d_out, int out_size) {
    const float* X = (const float*)d_in[0];   // source [8192, 256]
    const float* Y = (const float*)d_in[1];   // target [8192, 256]
    float* out = (float*)d_out;

    // gemm first: shifts the fixed ncu capture window onto the LSE kernels
    dim3 gg(NPT / BN, NPT / BM);
    gemm_q_kernel<<<gg, 256>>>(X, Y);

    norms_kernel<<<NPT / 8, 256>>>(X, 0);
    norms_kernel<<<NPT / 8, 256>>>(Y, 1);
    init_kernel<<<NPT / 256, 256>>>();

    dim3 cg(4, 128);
    for (int it = 0; it < 50; ++it) {
        row_lse_kernel<<<NPT / ROWS_PER_CTA, 256>>>(0);  // u <- v  (rows of C)
        col_lse_kernel<<<cg, 256>>>();                    // v partials (cols of C)
        col_combine_kernel<<<NPT / 256, 256>>>();         // v <- combine
    }
    row_lse_kernel<<<NPT / ROWS_PER_CTA, 256>>>(1);      // S_i with final v
    final_kernel<<<1, 256>>>(out);
}

// round 7
// speedup vs baseline: 2.0948x; 1.2135x over previous
#include <cuda_runtime.h>
#include <cstdint>

#define NPT 8192          // points per side
#define DIM 256           // feature dim
#define LOG2E  1.4426950408889634f
#define LN2    0.6931471805599453f
#define LOGN   9.0109133472f          // log(8192)
#define KS     (1.4426950408889634f / 64.0f)   // (q/128)*2*log2e : dequant*log2e fused
#define MAGB   0x4B000000u            // 2^23 magic base
#define MAGF   8421376.0f             // 2^23 + 32768 (exact in f32)
#define W2OFF  (8421376.0f * (1.4426950408889634f / 64.0f))  // MAGF*KS fold constant
#define NEG_INF (-__int_as_float(0x7f800000))
#define N_SAFE 3                      // iterations with online-max (also record maxes)

// ---------------- device scratch ----------------
__device__ unsigned short gC [(size_t)NPT * NPT]; // u16 = round(128*x.y) + 32768
__device__ float  gA[NPT], gB[NPT];               // squared norms
__device__ float  gU[NPT], gV[NPT], gS[NPT];
__device__ float  gMU[NPT], gMV[NPT];             // row/col max trackers (base-2 z units)
__device__ float  gPM[128 * NPT], gPS[128 * NPT]; // column-LSE partials (128 i-blocks)

// ---------------- helpers ----------------
__device__ __forceinline__ float ex2(float x) {
    float r; asm("ex2.approx.ftz.f32 %0, %1;" : "=f"(r) : "f"(x)); return r;
}

// branchless online log-sum-exp update (base-2 domain), exactly one EX2
#define BUPD(m, s, z) do {                        \
    float _d = (z) - (m);                         \
    float _e = ex2(0.0f - fabsf(_d));             \
    bool  _p = _d > 0.0f;                         \
    float _fa = _p ? _e : 1.0f;                   \
    float _fb = _p ? 1.0f : _e;                   \
    (s) = fmaf((s), _fa, _fb);                    \
    (m) = fmaxf((m), (z));                        \
} while (0)

// exact unpack (safe kernels): two offset-binary u16 -> floats == q
#define UNPK2(w, flo, fhi) do {                               \
    unsigned _lo = ((w) & 0x0000FFFFu) | MAGB;                \
    unsigned _hi = __byte_perm((w), MAGB, 0x7432);            \
    flo = __uint_as_float(_lo) - MAGF;                        \
    fhi = __uint_as_float(_hi) - MAGF;                        \
} while (0)

// raw unpack (fast kernels): floats == 2^23 + u16 (offset folded into w')
#define UNPKR(w, flo, fhi) do {                               \
    flo = __uint_as_float(((w) & 0x0000FFFFu) | MAGB);        \
    fhi = __uint_as_float(__byte_perm((w), MAGB, 0x7432));    \
} while (0)

// fast fixed-shift update: s += 2^(z-Z0); track max
#define FUPD(t, s, z, Z0) do {                    \
    (t) = fmaxf((t), (z));                        \
    (s) += ex2((z) - (Z0));                       \
} while (0)

// ---------------- squared norms ----------------
__global__ __launch_bounds__(256) void norms_kernel(const float* __restrict__ X, int which) {
    int warp = threadIdx.x >> 5, lane = threadIdx.x & 31;
    int row  = blockIdx.x * 8 + warp;
    const float4* xp = (const float4*)(X + (size_t)row * DIM);
    float ss = 0.0f;
    #pragma unroll
    for (int c = lane; c < DIM / 4; c += 32) {
        float4 t = xp[c];
        ss += t.x * t.x + t.y * t.y + t.z * t.z + t.w * t.w;
    }
    #pragma unroll
    for (int off = 16; off; off >>= 1)
        ss += __shfl_xor_sync(0xffffffffu, ss, off);
    if (lane == 0) { if (which) gB[row] = ss; else gA[row] = ss; }
}

__global__ void init_kernel() {
    int j = blockIdx.x * 256 + threadIdx.x;
    gV[j] = -gB[j];
    gU[j] = -gA[j];
}

// ---------------- GEMM: u16 = round(128 * X Y^T) + 32768 ----------------
#define BM 128
#define BN 128
#define BK 16

__device__ __forceinline__ unsigned pack2(int a, int b) {
    return ((unsigned)a & 0xffffu) | (((unsigned)b & 0xffffu) << 16);
}

__global__ __launch_bounds__(256) void gemm_q_kernel(const float* __restrict__ X,
                                                     const float* __restrict__ Y) {
    __shared__ float As[BK][BM + 4];
    __shared__ float Bs[BK][BN + 4];
    int tid = threadIdx.x;
    int tx = tid & 15, ty = tid >> 4;
    int bi = blockIdx.y * BM, bj = blockIdx.x * BN;

    float acc[8][8];
    #pragma unroll
    for (int r = 0; r < 8; ++r)
        #pragma unroll
        for (int c = 0; c < 8; ++c) acc[r][c] = 0.0f;

    for (int k0 = 0; k0 < DIM; k0 += BK) {
        #pragma unroll
        for (int q = 0; q < 2; ++q) {
            int idx = tid + q * 256;        // 0..511
            int row = idx >> 2;             // 0..127
            int kf  = (idx & 3) << 2;       // 0,4,8,12
            float4 av = *(const float4*)&X[(size_t)(bi + row) * DIM + k0 + kf];
            As[kf + 0][row] = av.x; As[kf + 1][row] = av.y;
            As[kf + 2][row] = av.z; As[kf + 3][row] = av.w;
            float4 bv = *(const float4*)&Y[(size_t)(bj + row) * DIM + k0 + kf];
            Bs[kf + 0][row] = bv.x; Bs[kf + 1][row] = bv.y;
            Bs[kf + 2][row] = bv.z; Bs[kf + 3][row] = bv.w;
        }
        __syncthreads();
        #pragma unroll
        for (int kk = 0; kk < BK; ++kk) {
            float ra[8], rb[8];
            *(float4*)&ra[0] = *(const float4*)&As[kk][ty * 8];
            *(float4*)&ra[4] = *(const float4*)&As[kk][ty * 8 + 4];
            *(float4*)&rb[0] = *(const float4*)&Bs[kk][tx * 8];
            *(float4*)&rb[4] = *(const float4*)&Bs[kk][tx * 8 + 4];
            #pragma unroll
            for (int r = 0; r < 8; ++r)
                #pragma unroll
                for (int c = 0; c < 8; ++c)
                    acc[r][c] = fmaf(ra[r], rb[c], acc[r][c]);
        }
        __syncthreads();
    }

    int row_i = bi + ty * 8, col_j = bj + tx * 8;
    #pragma unroll
    for (int r = 0; r < 8; ++r) {
        int q0[8];
        #pragma unroll
        for (int c = 0; c < 8; ++c) {
            int qi = __float2int_rn(acc[r][c] * 128.0f);
            q0[c] = max(-32767, min(32767, qi)) + 32768;   // offset-binary
        }
        uint4 pk;
        pk.x = pack2(q0[0], q0[1]); pk.y = pack2(q0[2], q0[3]);
        pk.z = pack2(q0[4], q0[5]); pk.w = pack2(q0[6], q0[7]);
        *(uint4*)&gC[(size_t)(row_i + r) * NPT + col_j] = pk;
    }
}

#define ROWS_PER_CTA 8
#define IB_ROWS 64

// ---------------- SAFE row logsumexp (records row max) ----------------
__global__ __launch_bounds__(256) void row_lse_safe(int mode) {
    __shared__ float w2[NPT];
    float* __restrict__ out = mode ? gS : gU;

    int tid = threadIdx.x;
    const float4* w4 = (const float4*)gV;
    for (int idx = tid; idx < NPT / 4; idx += 256) {
        float4 t = w4[idx];
        t.x *= LOG2E; t.y *= LOG2E; t.z *= LOG2E; t.w *= LOG2E;
        ((float4*)w2)[idx] = t;
    }
    __syncthreads();

    int warp = tid >> 5, lane = tid & 31;
    int i = blockIdx.x * ROWS_PER_CTA + warp;
    const uint4* __restrict__ rowp = (const uint4*)(gC + (size_t)i * NPT);

    float m0 = NEG_INF, s0 = 0.0f, m1 = NEG_INF, s1 = 0.0f;
    float m2 = NEG_INF, s2 = 0.0f, m3 = NEG_INF, s3 = 0.0f;

    #pragma unroll 4
    for (int c = 0; c < 32; ++c) {
        int idx = c * 32 + lane;
        uint4 rw = __ldcs(rowp + idx);
        const float4* wv = (const float4*)(w2 + (size_t)idx * 8);
        float4 wa = wv[0], wb = wv[1];
        float f0, f1;
        UNPK2(rw.x, f0, f1);
        BUPD(m0, s0, fmaf(f0, KS, wa.x)); BUPD(m1, s1, fmaf(f1, KS, wa.y));
        UNPK2(rw.y, f0, f1);
        BUPD(m2, s2, fmaf(f0, KS, wa.z)); BUPD(m3, s3, fmaf(f1, KS, wa.w));
        UNPK2(rw.z, f0, f1);
        BUPD(m0, s0, fmaf(f0, KS, wb.x)); BUPD(m1, s1, fmaf(f1, KS, wb.y));
        UNPK2(rw.w, f0, f1);
        BUPD(m2, s2, fmaf(f0, KS, wb.z)); BUPD(m3, s3, fmaf(f1, KS, wb.w));
    }

    float ma = fmaxf(m0, m1);
    float sa = s0 * ex2(m0 - ma) + s1 * ex2(m1 - ma);
    float mb = fmaxf(m2, m3);
    float sb = s2 * ex2(m2 - mb) + s3 * ex2(m3 - mb);
    float m = fmaxf(ma, mb);
    float s = sa * ex2(ma - m) + sb * ex2(mb - m);
    #pragma unroll
    for (int off = 16; off; off >>= 1) {
        float mo = __shfl_xor_sync(0xffffffffu, m, off);
        float so = __shfl_xor_sync(0xffffffffu, s, off);
        float mn = fmaxf(m, mo);
        s = s * ex2(m - mn) + so * ex2(mo - mn);
        m = mn;
    }
    if (lane == 0) { out[i] = LOGN - LN2 * (m + log2f(s)); gMU[i] = m; }
}

// ---------------- FAST row logsumexp (fixed shift Z0 = gMU) ----------------
__global__ __launch_bounds__(256) void row_lse_fast(int mode) {
    __shared__ float w2[NPT];
    float* __restrict__ out = mode ? gS : gU;

    int tid = threadIdx.x;
    const float4* w4 = (const float4*)gV;
    for (int idx = tid; idx < NPT / 4; idx += 256) {
        float4 t = w4[idx];
        t.x = fmaf(t.x, LOG2E, -W2OFF); t.y = fmaf(t.y, LOG2E, -W2OFF);
        t.z = fmaf(t.z, LOG2E, -W2OFF); t.w = fmaf(t.w, LOG2E, -W2OFF);
        ((float4*)w2)[idx] = t;
    }
    __syncthreads();

    int warp = tid >> 5, lane = tid & 31;
    int i = blockIdx.x * ROWS_PER_CTA + warp;
    float Z0 = gMU[i];
    const uint4* __restrict__ rowp = (const uint4*)(gC + (size_t)i * NPT);

    float s0 = 0.0f, s1 = 0.0f, s2 = 0.0f, s3 = 0.0f;
    float t0 = NEG_INF, t1 = NEG_INF, t2 = NEG_INF, t3 = NEG_INF;

    #pragma unroll 4
    for (int c = 0; c < 32; ++c) {
        int idx = c * 32 + lane;
        uint4 rw = __ldcs(rowp + idx);
        const float4* wv = (const float4*)(w2 + (size_t)idx * 8);
        float4 wa = wv[0], wb = wv[1];
        float f0, f1;
        UNPKR(rw.x, f0, f1);
        FUPD(t0, s0, fmaf(f0, KS, wa.x), Z0); FUPD(t1, s1, fmaf(f1, KS, wa.y), Z0);
        UNPKR(rw.y, f0, f1);
        FUPD(t2, s2, fmaf(f0, KS, wa.z), Z0); FUPD(t3, s3, fmaf(f1, KS, wa.w), Z0);
        UNPKR(rw.z, f0, f1);
        FUPD(t0, s0, fmaf(f0, KS, wb.x), Z0); FUPD(t1, s1, fmaf(f1, KS, wb.y), Z0);
        UNPKR(rw.w, f0, f1);
        FUPD(t2, s2, fmaf(f0, KS, wb.z), Z0); FUPD(t3, s3, fmaf(f1, KS, wb.w), Z0);
    }

    float s = (s0 + s1) + (s2 + s3);
    float t = fmaxf(fmaxf(t0, t1), fmaxf(t2, t3));
    #pragma unroll
    for (int off = 16; off; off >>= 1) {
        s += __shfl_xor_sync(0xffffffffu, s, off);
        t = fmaxf(t, __shfl_xor_sync(0xffffffffu, t, off));
    }
    if (lane == 0) { out[i] = LOGN - LN2 * (Z0 + log2f(s)); gMU[i] = t; }
}

// ---------------- SAFE column logsumexp + combine ----------------
__global__ __launch_bounds__(256) void col_lse_safe() {
    __shared__ float su[IB_ROWS];
    int tid = threadIdx.x;
    int jb = blockIdx.x, ib = blockIdx.y;
    int i0 = ib * IB_ROWS;

    if (tid < IB_ROWS) su[tid] = gU[i0 + tid] * LOG2E;
    __syncthreads();

    int j0 = jb * 2048 + tid * 8;
    const uint4* __restrict__ Cp = (const uint4*)(gC + (size_t)i0 * NPT + j0);

    float m[8], s[8];
    #pragma unroll
    for (int k = 0; k < 8; ++k) { m[k] = NEG_INF; s[k] = 0.0f; }

    #pragma unroll 4
    for (int ii = 0; ii < IB_ROWS; ++ii) {
        uint4 rw = __ldcs(Cp + (size_t)ii * (NPT / 8));
        float u = su[ii];
        float f0, f1;
        UNPK2(rw.x, f0, f1);
        BUPD(m[0], s[0], fmaf(f0, KS, u)); BUPD(m[1], s[1], fmaf(f1, KS, u));
        UNPK2(rw.y, f0, f1);
        BUPD(m[2], s[2], fmaf(f0, KS, u)); BUPD(m[3], s[3], fmaf(f1, KS, u));
        UNPK2(rw.z, f0, f1);
        BUPD(m[4], s[4], fmaf(f0, KS, u)); BUPD(m[5], s[5], fmaf(f1, KS, u));
        UNPK2(rw.w, f0, f1);
        BUPD(m[6], s[6], fmaf(f0, KS, u)); BUPD(m[7], s[7], fmaf(f1, KS, u));
    }

    float* pm = &gPM[(size_t)ib * NPT + j0];
    float* ps = &gPS[(size_t)ib * NPT + j0];
    #pragma unroll
    for (int k = 0; k < 2; ++k) {
        *(float4*)&pm[k * 4] = make_float4(m[k*4+0], m[k*4+1], m[k*4+2], m[k*4+3]);
        *(float4*)&ps[k * 4] = make_float4(s[k*4+0], s[k*4+1], s[k*4+2], s[k*4+3]);
    }
}

__global__ __launch_bounds__(256) void col_combine_safe() {
    int j = blockIdx.x * 256 + threadIdx.x;
    float m = NEG_INF, s = 0.0f;
    #pragma unroll 8
    for (int p = 0; p < 128; ++p) {
        float mp = gPM[(size_t)p * NPT + j];
        float sp = gPS[(size_t)p * NPT + j];
        float mn = fmaxf(m, mp);
        s = s * ex2(m - mn) + sp * ex2(mp - mn);
        m = mn;
    }
    gV[j] = LOGN - LN2 * (m + log2f(s));
    gMV[j] = m;
}

// ---------------- FAST column logsumexp + combine ----------------
__global__ __launch_bounds__(256) void col_lse_fast() {
    __shared__ float su[IB_ROWS];
    int tid = threadIdx.x;
    int jb = blockIdx.x, ib = blockIdx.y;
    int i0 = ib * IB_ROWS;

    if (tid < IB_ROWS) su[tid] = fmaf(gU[i0 + tid], LOG2E, -W2OFF);
    __syncthreads();

    int j0 = jb * 2048 + tid * 8;
    const uint4* __restrict__ Cp = (const uint4*)(gC + (size_t)i0 * NPT + j0);

    float Z0[8];
    *(float4*)&Z0[0] = *(const float4*)&gMV[j0];
    *(float4*)&Z0[4] = *(const float4*)&gMV[j0 + 4];

    float m[8], s[8];
    #pragma unroll
    for (int k = 0; k < 8; ++k) { m[k] = NEG_INF; s[k] = 0.0f; }

    #pragma unroll 4
    for (int ii = 0; ii < IB_ROWS; ++ii) {
        uint4 rw = __ldcs(Cp + (size_t)ii * (NPT / 8));
        float u = su[ii];
        float f0, f1;
        UNPKR(rw.x, f0, f1);
        FUPD(m[0], s[0], fmaf(f0, KS, u), Z0[0]); FUPD(m[1], s[1], fmaf(f1, KS, u), Z0[1]);
        UNPKR(rw.y, f0, f1);
        FUPD(m[2], s[2], fmaf(f0, KS, u), Z0[2]); FUPD(m[3], s[3], fmaf(f1, KS, u), Z0[3]);
        UNPKR(rw.z, f0, f1);
        FUPD(m[4], s[4], fmaf(f0, KS, u), Z0[4]); FUPD(m[5], s[5], fmaf(f1, KS, u), Z0[5]);
        UNPKR(rw.w, f0, f1);
        FUPD(m[6], s[6], fmaf(f0, KS, u), Z0[6]); FUPD(m[7], s[7], fmaf(f1, KS, u), Z0[7]);
    }

    float* pm = &gPM[(size_t)ib * NPT + j0];
    float* ps = &gPS[(size_t)ib * NPT + j0];
    #pragma unroll
    for (int k = 0; k < 2; ++k) {
        *(float4*)&pm[k * 4] = make_float4(m[k*4+0], m[k*4+1], m[k*4+2], m[k*4+3]);
        *(float4*)&ps[k * 4] = make_float4(s[k*4+0], s[k*4+1], s[k*4+2], s[k*4+3]);
    }
}

__global__ __launch_bounds__(256) void col_combine_fast() {
    int j = blockIdx.x * 256 + threadIdx.x;
    float m = NEG_INF, s = 0.0f;
    #pragma unroll 8
    for (int p = 0; p < 128; ++p) {
        s += gPS[(size_t)p * NPT + j];
        m = fmaxf(m, gPM[(size_t)p * NPT + j]);
    }
    float Z0 = gMV[j];
    gV[j] = LOGN - LN2 * (Z0 + log2f(s));
    gMV[j] = m;
}

// ---------------- final value reduction ----------------
// value = sum_i (a_i + u_i) * exp(u_i - LOGN - S_i) + (1/N) * sum_j (b_j + v_j)
__global__ __launch_bounds__(256) void final_kernel(float* __restrict__ out) {
    __shared__ float red[256];
    int tid = threadIdx.x;
    float acc = 0.0f;
    for (int i = tid; i < NPT; i += 256) {
        float fi = gA[i] + gU[i];
        float ri = expf(gU[i] - LOGN - gS[i]);
        float gj = gB[i] + gV[i];
        acc += fi * ri + gj * (1.0f / NPT);
    }
    red[tid] = acc;
    __syncthreads();
    #pragma unroll
    for (int st = 128; st; st >>= 1) {
        if (tid < st) red[tid] += red[tid + st];
        __syncthreads();
    }
    if (tid == 0) out[0] = sqrtf(red[0]);
}

// ---------------- launch ----------------
extern "C" void kernel_launch(void* const* d_in, const int* in_sizes, int n_in,
                              void* d_out, int out_size) {
    const float* X = (const float*)d_in[0];   // source [8192, 256]
    const float* Y = (const float*)d_in[1];   // target [8192, 256]
    float* out = (float*)d_out;

    dim3 gg(NPT / BN, NPT / BM);
    gemm_q_kernel<<<gg, 256>>>(X, Y);

    norms_kernel<<<NPT / 8, 256>>>(X, 0);
    norms_kernel<<<NPT / 8, 256>>>(Y, 1);
    init_kernel<<<NPT / 256, 256>>>();

    dim3 cg(4, 128);
    for (int it = 0; it < N_SAFE; ++it) {
        row_lse_safe<<<NPT / ROWS_PER_CTA, 256>>>(0);
        col_lse_safe<<<cg, 256>>>();
        col_combine_safe<<<NPT / 256, 256>>>();
    }
    for (int it = N_SAFE; it < 50; ++it) {
        row_lse_fast<<<NPT / ROWS_PER_CTA, 256>>>(0);
        col_lse_fast<<<cg, 256>>>();
        col_combine_fast<<<NPT / 256, 256>>>();
    }
    row_lse_fast<<<NPT / ROWS_PER_CTA, 256>>>(1);   // S_i with final v
    final_kernel<<<1, 256>>>(out);
}

// round 9
// speedup vs baseline: 2.3688x; 1.1308x over previous
#include <cuda_runtime.h>
#include <cuda_bf16.h>
#include <cstdint>

#define NPT 8192          // points per side
#define DIM 256           // feature dim
#define KEXT 768          // split-K for bf16 hi/lo GEMM (3 x 256)
#define LOG2E  1.4426950408889634f
#define LN2    0.6931471805599453f
#define LOGN   9.0109133472f          // log(8192)
#define KS     (1.4426950408889634f / 64.0f)   // (q/128)*2*log2e
#define MAGB   0x4B000000u            // 2^23 magic base
#define MAGF   8421376.0f             // 2^23 + 32768 (exact in f32)
#define W2OFF  (8421376.0f * (1.4426950408889634f / 64.0f))  // MAGF*KS fold
#define NEG_INF (-__int_as_float(0x7f800000))
#define N_SAFE 3

// ---------------- device scratch ----------------
__device__ __align__(16) unsigned short gC [(size_t)NPT * NPT];
__device__ __align__(16) __nv_bfloat16 gAx[(size_t)NPT * KEXT]; // [Xhi | Xlo | Xhi]
__device__ __align__(16) __nv_bfloat16 gBy[(size_t)NPT * KEXT]; // [Yhi | Yhi | Ylo]
__device__ float  gA[NPT], gB[NPT];
__device__ float  gU[NPT], gV[NPT], gS[NPT];
__device__ __align__(16) float gMU[NPT], gMV[NPT]; // frozen per-row/col shifts
__device__ __align__(16) float gPM[128 * NPT], gPS[128 * NPT];

// ---------------- helpers ----------------
__device__ __forceinline__ float ex2(float x) {
    float r; asm("ex2.approx.ftz.f32 %0, %1;" : "=f"(r) : "f"(x)); return r;
}

#define BUPD(m, s, z) do {                        \
    float _d = (z) - (m);                         \
    float _e = ex2(0.0f - fabsf(_d));             \
    bool  _p = _d > 0.0f;                         \
    float _fa = _p ? _e : 1.0f;                   \
    float _fb = _p ? 1.0f : _e;                   \
    (s) = fmaf((s), _fa, _fb);                    \
    (m) = fmaxf((m), (z));                        \
} while (0)

// exact unpack (safe kernels)
#define UNPK2(w, flo, fhi) do {                               \
    unsigned _lo = ((w) & 0x0000FFFFu) | MAGB;                \
    unsigned _hi = __byte_perm((w), MAGB, 0x7432);            \
    flo = __uint_as_float(_lo) - MAGF;                        \
    fhi = __uint_as_float(_hi) - MAGF;                        \
} while (0)

// raw unpack (fast kernels): floats == 2^23 + u16
#define UNPKR(w, flo, fhi) do {                               \
    flo = __uint_as_float(((w) & 0x0000FFFFu) | MAGB);        \
    fhi = __uint_as_float(__byte_perm((w), MAGB, 0x7432));    \
} while (0)

__device__ __forceinline__ unsigned pack2(int a, int b) {
    return ((unsigned)a & 0xffffu) | (((unsigned)b & 0xffffu) << 16);
}

// ---------------- squared norms ----------------
__global__ __launch_bounds__(256) void norms_kernel(const float* __restrict__ X, int which) {
    int warp = threadIdx.x >> 5, lane = threadIdx.x & 31;
    int row  = blockIdx.x * 8 + warp;
    const float4* xp = (const float4*)(X + (size_t)row * DIM);
    float ss = 0.0f;
    #pragma unroll
    for (int c = lane; c < DIM / 4; c += 32) {
        float4 t = xp[c];
        ss += t.x * t.x + t.y * t.y + t.z * t.z + t.w * t.w;
    }
    #pragma unroll
    for (int off = 16; off; off >>= 1)
        ss += __shfl_xor_sync(0xffffffffu, ss, off);
    if (lane == 0) { if (which) gB[row] = ss; else gA[row] = ss; }
}

__global__ void init_kernel() {
    int j = blockIdx.x * 256 + threadIdx.x;
    gV[j] = -gB[j];
    gU[j] = -gA[j];
}

// ---------------- bf16 hi/lo conversion ----------------
__global__ __launch_bounds__(256) void convert_kernel(const float* __restrict__ X,
                                                      const float* __restrict__ Y) {
    int row = blockIdx.x;
    int c = threadIdx.x;
    float x = X[(size_t)row * DIM + c];
    __nv_bfloat16 h = __float2bfloat16(x);
    __nv_bfloat16 l = __float2bfloat16(x - __bfloat162float(h));
    gAx[(size_t)row * KEXT + c]       = h;
    gAx[(size_t)row * KEXT + 256 + c] = l;
    gAx[(size_t)row * KEXT + 512 + c] = h;
    float y = Y[(size_t)row * DIM + c];
    __nv_bfloat16 hy = __float2bfloat16(y);
    __nv_bfloat16 ly = __float2bfloat16(y - __bfloat162float(hy));
    gBy[(size_t)row * KEXT + c]       = hy;
    gBy[(size_t)row * KEXT + 256 + c] = hy;
    gBy[(size_t)row * KEXT + 512 + c] = ly;
}

// ---------------- tensor-core GEMM: q = round(128 * Ax By^T) + 32768 ----------------
#define GBK 32
#define ASTR 40   // smem row stride in bf16 (80B: conflict-free for ldmatrix)

__device__ __forceinline__ void ldsm4(unsigned* r, unsigned addr) {
    asm volatile("ldmatrix.sync.aligned.m8n8.x4.shared.b16 {%0,%1,%2,%3}, [%4];"
        : "=r"(r[0]), "=r"(r[1]), "=r"(r[2]), "=r"(r[3]) : "r"(addr));
}
__device__ __forceinline__ void mma16816(float* d, const unsigned* a, const unsigned* b) {
    asm volatile("mma.sync.aligned.m16n8k16.row.col.f32.bf16.bf16.f32 "
        "{%0,%1,%2,%3}, {%4,%5,%6,%7}, {%8,%9}, {%0,%1,%2,%3};"
        : "+f"(d[0]), "+f"(d[1]), "+f"(d[2]), "+f"(d[3])
        : "r"(a[0]), "r"(a[1]), "r"(a[2]), "r"(a[3]), "r"(b[0]), "r"(b[1]));
}
__device__ __forceinline__ int qz(float x) {
    int qi = __float2int_rn(x * 128.0f);
    return max(-32767, min(32767, qi)) + 32768;
}

__global__ __launch_bounds__(256) void gemm_mma_kernel() {
    __shared__ __align__(16) __nv_bfloat16 As[128 * ASTR];
    __shared__ __align__(16) __nv_bfloat16 Bs[128 * ASTR];
    int tid = threadIdx.x;
    int wid = tid >> 5, lane = tid & 31;
    int wm = wid >> 1, wn = wid & 1;          // warp tile (wm*32, wn*64)
    int bi = blockIdx.y * 128, bj = blockIdx.x * 128;

    const __nv_bfloat16* Ag = gAx + (size_t)bi * KEXT;
    const __nv_bfloat16* Bg = gBy + (size_t)bj * KEXT;

    float acc[2][8][4];
    #pragma unroll
    for (int t = 0; t < 2; ++t)
        #pragma unroll
        for (int n = 0; n < 8; ++n)
            #pragma unroll
            for (int k = 0; k < 4; ++k) acc[t][n][k] = 0.0f;

    uint4 pa[2], pb[2];

    #pragma unroll
    for (int q = 0; q < 2; ++q) {
        int idx = tid + q * 256;
        int row = idx >> 2, cs = (idx & 3) * 8;
        *(uint4*)(As + row * ASTR + cs) = *(const uint4*)(Ag + (size_t)row * KEXT + cs);
        *(uint4*)(Bs + row * ASTR + cs) = *(const uint4*)(Bg + (size_t)row * KEXT + cs);
    }
    __syncthreads();

    unsigned aBase = (unsigned)__cvta_generic_to_shared(As);
    unsigned bBase = (unsigned)__cvta_generic_to_shared(Bs);

    for (int it = 0; it < KEXT / GBK; ++it) {
        if (it < KEXT / GBK - 1) {
            int k0 = (it + 1) * GBK;
            #pragma unroll
            for (int q = 0; q < 2; ++q) {
                int idx = tid + q * 256;
                int row = idx >> 2, cs = (idx & 3) * 8;
                pa[q] = *(const uint4*)(Ag + (size_t)row * KEXT + k0 + cs);
                pb[q] = *(const uint4*)(Bg + (size_t)row * KEXT + k0 + cs);
            }
        }
        #pragma unroll
        for (int kk = 0; kk < 2; ++kk) {
            int k0 = kk * 16;
            unsigned af[2][4];
            #pragma unroll
            for (int t = 0; t < 2; ++t) {
                int row = wm * 32 + t * 16 + (lane & 15);
                int col = k0 + (lane >> 4) * 8;
                ldsm4(af[t], aBase + (row * ASTR + col) * 2);
            }
            unsigned bfm[4][4];
            #pragma unroll
            for (int t = 0; t < 4; ++t) {
                int nrow = wn * 64 + t * 16 + (lane & 7) + ((lane >> 4) & 1) * 8;
                int col  = k0 + ((lane >> 3) & 1) * 8;
                ldsm4(bfm[t], bBase + (nrow * ASTR + col) * 2);
            }
            #pragma unroll
            for (int t = 0; t < 2; ++t)
                #pragma unroll
                for (int n = 0; n < 8; ++n) {
                    unsigned bb[2];
                    bb[0] = bfm[n >> 1][(n & 1) * 2 + 0];
                    bb[1] = bfm[n >> 1][(n & 1) * 2 + 1];
                    mma16816(acc[t][n], af[t], bb);
                }
        }
        __syncthreads();
        if (it < KEXT / GBK - 1) {
            #pragma unroll
            for (int q = 0; q < 2; ++q) {
                int idx = tid + q * 256;
                int row = idx >> 2, cs = (idx & 3) * 8;
                *(uint4*)(As + row * ASTR + cs) = pa[q];
                *(uint4*)(Bs + row * ASTR + cs) = pb[q];
            }
            __syncthreads();
        }
    }

    #pragma unroll
    for (int t = 0; t < 2; ++t) {
        int r0 = bi + wm * 32 + t * 16 + (lane >> 2);
        #pragma unroll
        for (int n = 0; n < 8; ++n) {
            int col = bj + wn * 64 + n * 8 + (lane & 3) * 2;
            *(unsigned*)&gC[(size_t)r0 * NPT + col] =
                pack2(qz(acc[t][n][0]), qz(acc[t][n][1]));
            *(unsigned*)&gC[(size_t)(r0 + 8) * NPT + col] =
                pack2(qz(acc[t][n][2]), qz(acc[t][n][3]));
        }
    }
}

#define ROWS_PER_CTA 8
#define IB_ROWS 64

// ---------------- SAFE row logsumexp (records row max) ----------------
__global__ __launch_bounds__(256) void row_lse_safe(int mode) {
    __shared__ float w2[NPT];
    float* __restrict__ out = mode ? gS : gU;

    int tid = threadIdx.x;
    const float4* w4 = (const float4*)gV;
    for (int idx = tid; idx < NPT / 4; idx += 256) {
        float4 t = w4[idx];
        t.x *= LOG2E; t.y *= LOG2E; t.z *= LOG2E; t.w *= LOG2E;
        ((float4*)w2)[idx] = t;
    }
    __syncthreads();

    int warp = tid >> 5, lane = tid & 31;
    int i = blockIdx.x * ROWS_PER_CTA + warp;
    const uint4* __restrict__ rowp = (const uint4*)(gC + (size_t)i * NPT);

    float m0 = NEG_INF, s0 = 0.0f, m1 = NEG_INF, s1 = 0.0f;
    float m2 = NEG_INF, s2 = 0.0f, m3 = NEG_INF, s3 = 0.0f;

    #pragma unroll 4
    for (int c = 0; c < 32; ++c) {
        int idx = c * 32 + lane;
        uint4 rw = __ldcs(rowp + idx);
        const float4* wv = (const float4*)(w2 + (size_t)idx * 8);
        float4 wa = wv[0], wb = wv[1];
        float f0, f1;
        UNPK2(rw.x, f0, f1);
        BUPD(m0, s0, fmaf(f0, KS, wa.x)); BUPD(m1, s1, fmaf(f1, KS, wa.y));
        UNPK2(rw.y, f0, f1);
        BUPD(m2, s2, fmaf(f0, KS, wa.z)); BUPD(m3, s3, fmaf(f1, KS, wa.w));
        UNPK2(rw.z, f0, f1);
        BUPD(m0, s0, fmaf(f0, KS, wb.x)); BUPD(m1, s1, fmaf(f1, KS, wb.y));
        UNPK2(rw.w, f0, f1);
        BUPD(m2, s2, fmaf(f0, KS, wb.z)); BUPD(m3, s3, fmaf(f1, KS, wb.w));
    }

    float ma = fmaxf(m0, m1);
    float sa = s0 * ex2(m0 - ma) + s1 * ex2(m1 - ma);
    float mb = fmaxf(m2, m3);
    float sb = s2 * ex2(m2 - mb) + s3 * ex2(m3 - mb);
    float m = fmaxf(ma, mb);
    float s = sa * ex2(ma - m) + sb * ex2(mb - m);
    #pragma unroll
    for (int off = 16; off; off >>= 1) {
        float mo = __shfl_xor_sync(0xffffffffu, m, off);
        float so = __shfl_xor_sync(0xffffffffu, s, off);
        float mn = fmaxf(m, mo);
        s = s * ex2(m - mn) + so * ex2(mo - mn);
        m = mn;
    }
    if (lane == 0) { out[i] = LOGN - LN2 * (m + log2f(s)); gMU[i] = m; }
}

// ---------------- FAST row logsumexp (frozen per-row shift gMU[i]) ----------------
__global__ __launch_bounds__(256) void row_lse_fast(int mode) {
    __shared__ float w2[NPT];
    float* __restrict__ out = mode ? gS : gU;

    int tid = threadIdx.x;
    const float4* w4 = (const float4*)gV;
    for (int idx = tid; idx < NPT / 4; idx += 256) {
        float4 t = w4[idx];
        t.x = fmaf(t.x, LOG2E, -W2OFF); t.y = fmaf(t.y, LOG2E, -W2OFF);
        t.z = fmaf(t.z, LOG2E, -W2OFF); t.w = fmaf(t.w, LOG2E, -W2OFF);
        ((float4*)w2)[idx] = t;
    }
    __syncthreads();

    int warp = tid >> 5, lane = tid & 31;
    int i = blockIdx.x * ROWS_PER_CTA + warp;
    float Z0 = gMU[i];
    float nZ0 = -Z0;
    const uint4* __restrict__ rowp = (const uint4*)(gC + (size_t)i * NPT);

    float s0 = 0.0f, s1 = 0.0f, s2 = 0.0f, s3 = 0.0f;

    #pragma unroll 4
    for (int c = 0; c < 32; ++c) {
        int idx = c * 32 + lane;
        uint4 rw = __ldcs(rowp + idx);
        const float4* wv = (const float4*)(w2 + (size_t)idx * 8);
        float4 wa = wv[0], wb = wv[1];
        float f0, f1;
        UNPKR(rw.x, f0, f1);
        s0 += ex2(fmaf(f0, KS, wa.x) + nZ0); s1 += ex2(fmaf(f1, KS, wa.y) + nZ0);
        UNPKR(rw.y, f0, f1);
        s2 += ex2(fmaf(f0, KS, wa.z) + nZ0); s3 += ex2(fmaf(f1, KS, wa.w) + nZ0);
        UNPKR(rw.z, f0, f1);
        s0 += ex2(fmaf(f0, KS, wb.x) + nZ0); s1 += ex2(fmaf(f1, KS, wb.y) + nZ0);
        UNPKR(rw.w, f0, f1);
        s2 += ex2(fmaf(f0, KS, wb.z) + nZ0); s3 += ex2(fmaf(f1, KS, wb.w) + nZ0);
    }

    float s = (s0 + s1) + (s2 + s3);
    #pragma unroll
    for (int off = 16; off; off >>= 1)
        s += __shfl_xor_sync(0xffffffffu, s, off);
    if (lane == 0) out[i] = LOGN - LN2 * (Z0 + log2f(s));
}

// ---------------- SAFE column logsumexp + combine ----------------
__global__ __launch_bounds__(256) void col_lse_safe() {
    __shared__ float su[IB_ROWS];
    int tid = threadIdx.x;
    int jb = blockIdx.x, ib = blockIdx.y;
    int i0 = ib * IB_ROWS;

    if (tid < IB_ROWS) su[tid] = gU[i0 + tid] * LOG2E;
    __syncthreads();

    int j0 = jb * 2048 + tid * 8;
    const uint4* __restrict__ Cp = (const uint4*)(gC + (size_t)i0 * NPT + j0);

    float m[8], s[8];
    #pragma unroll
    for (int k = 0; k < 8; ++k) { m[k] = NEG_INF; s[k] = 0.0f; }

    #pragma unroll 4
    for (int ii = 0; ii < IB_ROWS; ++ii) {
        uint4 rw = __ldcs(Cp + (size_t)ii * (NPT / 8));
        float u = su[ii];
        float f0, f1;
        UNPK2(rw.x, f0, f1);
        BUPD(m[0], s[0], fmaf(f0, KS, u)); BUPD(m[1], s[1], fmaf(f1, KS, u));
        UNPK2(rw.y, f0, f1);
        BUPD(m[2], s[2], fmaf(f0, KS, u)); BUPD(m[3], s[3], fmaf(f1, KS, u));
        UNPK2(rw.z, f0, f1);
        BUPD(m[4], s[4], fmaf(f0, KS, u)); BUPD(m[5], s[5], fmaf(f1, KS, u));
        UNPK2(rw.w, f0, f1);
        BUPD(m[6], s[6], fmaf(f0, KS, u)); BUPD(m[7], s[7], fmaf(f1, KS, u));
    }

    float* pm = &gPM[(size_t)ib * NPT + j0];
    float* ps = &gPS[(size_t)ib * NPT + j0];
    #pragma unroll
    for (int k = 0; k < 2; ++k) {
        *(float4*)&pm[k * 4] = make_float4(m[k*4+0], m[k*4+1], m[k*4+2], m[k*4+3]);
        *(float4*)&ps[k * 4] = make_float4(s[k*4+0], s[k*4+1], s[k*4+2], s[k*4+3]);
    }
}

__global__ __launch_bounds__(256) void col_combine_safe() {
    int j = blockIdx.x * 256 + threadIdx.x;
    float m = NEG_INF, s = 0.0f;
    #pragma unroll 8
    for (int p = 0; p < 128; ++p) {
        float mp = gPM[(size_t)p * NPT + j];
        float sp = gPS[(size_t)p * NPT + j];
        float mn = fmaxf(m, mp);
        s = s * ex2(m - mn) + sp * ex2(mp - mn);
        m = mn;
    }
    gV[j] = LOGN - LN2 * (m + log2f(s));
    gMV[j] = m;
}

// ---------------- FAST column logsumexp + combine (frozen per-col gMV[j]) ----------------
__global__ __launch_bounds__(256) void col_lse_fast() {
    __shared__ float su[IB_ROWS];
    int tid = threadIdx.x;
    int jb = blockIdx.x, ib = blockIdx.y;
    int i0 = ib * IB_ROWS;

    if (tid < IB_ROWS) su[tid] = fmaf(gU[i0 + tid], LOG2E, -W2OFF);
    __syncthreads();

    int j0 = jb * 2048 + tid * 8;
    const uint4* __restrict__ Cp = (const uint4*)(gC + (size_t)i0 * NPT + j0);

    float nZ[8];
    {
        float4 za = *(const float4*)&gMV[j0];
        float4 zb = *(const float4*)&gMV[j0 + 4];
        nZ[0] = -za.x; nZ[1] = -za.y; nZ[2] = -za.z; nZ[3] = -za.w;
        nZ[4] = -zb.x; nZ[5] = -zb.y; nZ[6] = -zb.z; nZ[7] = -zb.w;
    }

    float s[8];
    #pragma unroll
    for (int k = 0; k < 8; ++k) s[k] = 0.0f;

    #pragma unroll 4
    for (int ii = 0; ii < IB_ROWS; ++ii) {
        uint4 rw = __ldcs(Cp + (size_t)ii * (NPT / 8));
        float u = su[ii];
        float f0, f1;
        UNPKR(rw.x, f0, f1);
        s[0] += ex2(fmaf(f0, KS, u) + nZ[0]); s[1] += ex2(fmaf(f1, KS, u) + nZ[1]);
        UNPKR(rw.y, f0, f1);
        s[2] += ex2(fmaf(f0, KS, u) + nZ[2]); s[3] += ex2(fmaf(f1, KS, u) + nZ[3]);
        UNPKR(rw.z, f0, f1);
        s[4] += ex2(fmaf(f0, KS, u) + nZ[4]); s[5] += ex2(fmaf(f1, KS, u) + nZ[5]);
        UNPKR(rw.w, f0, f1);
        s[6] += ex2(fmaf(f0, KS, u) + nZ[6]); s[7] += ex2(fmaf(f1, KS, u) + nZ[7]);
    }

    float* ps = &gPS[(size_t)ib * NPT + j0];
    #pragma unroll
    for (int k = 0; k < 2; ++k)
        *(float4*)&ps[k * 4] = make_float4(s[k*4+0], s[k*4+1], s[k*4+2], s[k*4+3]);
}

__global__ __launch_bounds__(256) void col_combine_fast() {
    int j = blockIdx.x * 256 + threadIdx.x;
    float s = 0.0f;
    #pragma unroll 8
    for (int p = 0; p < 128; ++p)
        s += gPS[(size_t)p * NPT + j];
    gV[j] = LOGN - LN2 * (gMV[j] + log2f(s));
}

// ---------------- final value reduction ----------------
__global__ __launch_bounds__(256) void final_kernel(float* __restrict__ out) {
    __shared__ float red[256];
    int tid = threadIdx.x;
    float acc = 0.0f;
    for (int i = tid; i < NPT; i += 256) {
        float fi = gA[i] + gU[i];
        float ri = expf(gU[i] - LOGN - gS[i]);
        float gj = gB[i] + gV[i];
        acc += fi * ri + gj * (1.0f / NPT);
    }
    red[tid] = acc;
    __syncthreads();
    #pragma unroll
    for (int st = 128; st; st >>= 1) {
        if (tid < st) red[tid] += red[tid + st];
        __syncthreads();
    }
    if (tid == 0) out[0] = sqrtf(red[0]);
}

// ---------------- launch ----------------
extern "C" void kernel_launch(void* const* d_in, const int* in_sizes, int n_in,
                              void* d_out, int out_size) {
    const float* X = (const float*)d_in[0];   // source [8192, 256]
    const float* Y = (const float*)d_in[1];   // target [8192, 256]
    float* out = (float*)d_out;

    convert_kernel<<<NPT, 256>>>(X, Y);
    dim3 gg(NPT / 128, NPT / 128);
    gemm_mma_kernel<<<gg, 256>>>();

    norms_kernel<<<NPT / 8, 256>>>(X, 0);
    norms_kernel<<<NPT / 8, 256>>>(Y, 1);
    init_kernel<<<NPT / 256, 256>>>();

    dim3 cg(4, 128);
    for (int it = 0; it < N_SAFE; ++it) {
        row_lse_safe<<<NPT / ROWS_PER_CTA, 256>>>(0);
        col_lse_safe<<<cg, 256>>>();
        col_combine_safe<<<NPT / 256, 256>>>();
    }
    for (int it = N_SAFE; it < 50; ++it) {
        row_lse_fast<<<NPT / ROWS_PER_CTA, 256>>>(0);
        col_lse_fast<<<cg, 256>>>();
        col_combine_fast<<<NPT / 256, 256>>>();
    }
    row_lse_fast<<<NPT / ROWS_PER_CTA, 256>>>(1);   // S_i with final v
    final_kernel<<<1, 256>>>(out);
}

// round 10
// speedup vs baseline: 2.5022x; 1.0563x over previous
#include <cuda_runtime.h>
#include <cuda_bf16.h>
#include <cstdint>

#define NPT 8192          // points per side
#define DIM 256           // feature dim
#define KEXT 768          // split-K for bf16 hi/lo GEMM (3 x 256)
#define LOG2E  1.4426950408889634f
#define LN2    0.6931471805599453f
#define LOGN   9.0109133472f          // log(8192)
#define KS     (1.4426950408889634f / 64.0f)   // (q/128)*2*log2e
#define MAGB   0x4B000000u            // 2^23 magic base
#define MAGF   8421376.0f             // 2^23 + 32768 (exact in f32)
#define W2OFF  (8421376.0f * (1.4426950408889634f / 64.0f))  // MAGF*KS fold
#define NEG_INF (-__int_as_float(0x7f800000))
#define N_SAFE 2

typedef unsigned long long ull;

// ---------------- device scratch ----------------
__device__ __align__(16) unsigned short gC [(size_t)NPT * NPT];
__device__ __align__(16) __nv_bfloat16 gAx[(size_t)NPT * KEXT]; // [Xhi | Xlo | Xhi]
__device__ __align__(16) __nv_bfloat16 gBy[(size_t)NPT * KEXT]; // [Yhi | Yhi | Ylo]
__device__ float  gA[NPT], gB[NPT];
__device__ float  gU[NPT], gV[NPT], gS[NPT];
__device__ __align__(16) float gMU[NPT], gMV[NPT]; // frozen per-row/col shifts
__device__ __align__(16) float gPM[128 * NPT], gPS[128 * NPT];

// ---------------- helpers ----------------
__device__ __forceinline__ float ex2(float x) {
    float r; asm("ex2.approx.ftz.f32 %0, %1;" : "=f"(r) : "f"(x)); return r;
}
__device__ __forceinline__ ull pkf2(float lo, float hi) {
    ull r; asm("mov.b64 %0, {%1,%2};" : "=l"(r) : "f"(lo), "f"(hi)); return r;
}
__device__ __forceinline__ ull pku2(unsigned lo, unsigned hi) {
    ull r; asm("mov.b64 %0, {%1,%2};" : "=l"(r) : "r"(lo), "r"(hi)); return r;
}
__device__ __forceinline__ void upkf2(ull v, float& lo, float& hi) {
    asm("mov.b64 {%0,%1}, %2;" : "=f"(lo), "=f"(hi) : "l"(v));
}
__device__ __forceinline__ ull fma2(ull a, ull b, ull c) {
    ull d; asm("fma.rn.f32x2 %0, %1, %2, %3;" : "=l"(d) : "l"(a), "l"(b), "l"(c)); return d;
}
__device__ __forceinline__ ull add2(ull a, ull b) {
    ull d; asm("add.rn.f32x2 %0, %1, %2;" : "=l"(d) : "l"(a), "l"(b)); return d;
}

#define BUPD(m, s, z) do {                        \
    float _d = (z) - (m);                         \
    float _e = ex2(0.0f - fabsf(_d));             \
    bool  _p = _d > 0.0f;                         \
    float _fa = _p ? _e : 1.0f;                   \
    float _fb = _p ? 1.0f : _e;                   \
    (s) = fmaf((s), _fa, _fb);                    \
    (m) = fmaxf((m), (z));                        \
} while (0)

// exact unpack (safe kernels)
#define UNPK2(w, flo, fhi) do {                               \
    unsigned _lo = ((w) & 0x0000FFFFu) | MAGB;                \
    unsigned _hi = __byte_perm((w), MAGB, 0x7432);            \
    flo = __uint_as_float(_lo) - MAGF;                        \
    fhi = __uint_as_float(_hi) - MAGF;                        \
} while (0)

// raw packed unpack (fast kernels): f32x2 == (2^23+u16_lo, 2^23+u16_hi)
#define UNPKP(w, q2) do {                                     \
    unsigned _lo = ((w) & 0x0000FFFFu) | MAGB;                \
    unsigned _hi = __byte_perm((w), MAGB, 0x7432);            \
    q2 = pku2(_lo, _hi);                                      \
} while (0)

__device__ __forceinline__ unsigned pack2(int a, int b) {
    return ((unsigned)a & 0xffffu) | (((unsigned)b & 0xffffu) << 16);
}

// ---------------- bf16 hi/lo conversion + squared norms (fused) ----------------
__global__ __launch_bounds__(256) void convert_kernel(const float* __restrict__ X,
                                                      const float* __restrict__ Y) {
    __shared__ float redx[8], redy[8];
    int row = blockIdx.x;
    int c = threadIdx.x;
    int warp = c >> 5, lane = c & 31;

    float x = X[(size_t)row * DIM + c];
    __nv_bfloat16 h = __float2bfloat16(x);
    __nv_bfloat16 l = __float2bfloat16(x - __bfloat162float(h));
    gAx[(size_t)row * KEXT + c]       = h;
    gAx[(size_t)row * KEXT + 256 + c] = l;
    gAx[(size_t)row * KEXT + 512 + c] = h;
    float y = Y[(size_t)row * DIM + c];
    __nv_bfloat16 hy = __float2bfloat16(y);
    __nv_bfloat16 ly = __float2bfloat16(y - __bfloat162float(hy));
    gBy[(size_t)row * KEXT + c]       = hy;
    gBy[(size_t)row * KEXT + 256 + c] = hy;
    gBy[(size_t)row * KEXT + 512 + c] = ly;

    float sx = x * x, sy = y * y;
    #pragma unroll
    for (int off = 16; off; off >>= 1) {
        sx += __shfl_xor_sync(0xffffffffu, sx, off);
        sy += __shfl_xor_sync(0xffffffffu, sy, off);
    }
    if (lane == 0) { redx[warp] = sx; redy[warp] = sy; }
    __syncthreads();
    if (c == 0) {
        float ax = 0.0f, ay = 0.0f;
        #pragma unroll
        for (int w = 0; w < 8; ++w) { ax += redx[w]; ay += redy[w]; }
        gA[row] = ax; gB[row] = ay;
    }
}

__global__ void init_kernel() {
    int j = blockIdx.x * 256 + threadIdx.x;
    gV[j] = -gB[j];
    gU[j] = -gA[j];
}

// ---------------- tensor-core GEMM: q = round(128 * Ax By^T) + 32768 ----------------
#define GBK 32
#define ASTR 40   // smem row stride in bf16 (80B: conflict-free for ldmatrix)

__device__ __forceinline__ void ldsm4(unsigned* r, unsigned addr) {
    asm volatile("ldmatrix.sync.aligned.m8n8.x4.shared.b16 {%0,%1,%2,%3}, [%4];"
        : "=r"(r[0]), "=r"(r[1]), "=r"(r[2]), "=r"(r[3]) : "r"(addr));
}
__device__ __forceinline__ void mma16816(float* d, const unsigned* a, const unsigned* b) {
    asm volatile("mma.sync.aligned.m16n8k16.row.col.f32.bf16.bf16.f32 "
        "{%0,%1,%2,%3}, {%4,%5,%6,%7}, {%8,%9}, {%0,%1,%2,%3};"
        : "+f"(d[0]), "+f"(d[1]), "+f"(d[2]), "+f"(d[3])
        : "r"(a[0]), "r"(a[1]), "r"(a[2]), "r"(a[3]), "r"(b[0]), "r"(b[1]));
}
__device__ __forceinline__ int qz(float x) {
    int qi = __float2int_rn(x * 128.0f);
    return max(-32767, min(32767, qi)) + 32768;
}

__global__ __launch_bounds__(256) void gemm_mma_kernel() {
    __shared__ __align__(16) __nv_bfloat16 As[128 * ASTR];
    __shared__ __align__(16) __nv_bfloat16 Bs[128 * ASTR];
    int tid = threadIdx.x;
    int wid = tid >> 5, lane = tid & 31;
    int wm = wid >> 1, wn = wid & 1;
    int bi = blockIdx.y * 128, bj = blockIdx.x * 128;

    const __nv_bfloat16* Ag = gAx + (size_t)bi * KEXT;
    const __nv_bfloat16* Bg = gBy + (size_t)bj * KEXT;

    float acc[2][8][4];
    #pragma unroll
    for (int t = 0; t < 2; ++t)
        #pragma unroll
        for (int n = 0; n < 8; ++n)
            #pragma unroll
            for (int k = 0; k < 4; ++k) acc[t][n][k] = 0.0f;

    uint4 pa[2], pb[2];

    #pragma unroll
    for (int q = 0; q < 2; ++q) {
        int idx = tid + q * 256;
        int row = idx >> 2, cs = (idx & 3) * 8;
        *(uint4*)(As + row * ASTR + cs) = *(const uint4*)(Ag + (size_t)row * KEXT + cs);
        *(uint4*)(Bs + row * ASTR + cs) = *(const uint4*)(Bg + (size_t)row * KEXT + cs);
    }
    __syncthreads();

    unsigned aBase = (unsigned)__cvta_generic_to_shared(As);
    unsigned bBase = (unsigned)__cvta_generic_to_shared(Bs);

    for (int it = 0; it < KEXT / GBK; ++it) {
        if (it < KEXT / GBK - 1) {
            int k0 = (it + 1) * GBK;
            #pragma unroll
            for (int q = 0; q < 2; ++q) {
                int idx = tid + q * 256;
                int row = idx >> 2, cs = (idx & 3) * 8;
                pa[q] = *(const uint4*)(Ag + (size_t)row * KEXT + k0 + cs);
                pb[q] = *(const uint4*)(Bg + (size_t)row * KEXT + k0 + cs);
            }
        }
        #pragma unroll
        for (int kk = 0; kk < 2; ++kk) {
            int k0 = kk * 16;
            unsigned af[2][4];
            #pragma unroll
            for (int t = 0; t < 2; ++t) {
                int row = wm * 32 + t * 16 + (lane & 15);
                int col = k0 + (lane >> 4) * 8;
                ldsm4(af[t], aBase + (row * ASTR + col) * 2);
            }
            unsigned bfm[4][4];
            #pragma unroll
            for (int t = 0; t < 4; ++t) {
                int nrow = wn * 64 + t * 16 + (lane & 7) + ((lane >> 4) & 1) * 8;
                int col  = k0 + ((lane >> 3) & 1) * 8;
                ldsm4(bfm[t], bBase + (nrow * ASTR + col) * 2);
            }
            #pragma unroll
            for (int t = 0; t < 2; ++t)
                #pragma unroll
                for (int n = 0; n < 8; ++n) {
                    unsigned bb[2];
                    bb[0] = bfm[n >> 1][(n & 1) * 2 + 0];
                    bb[1] = bfm[n >> 1][(n & 1) * 2 + 1];
                    mma16816(acc[t][n], af[t], bb);
                }
        }
        __syncthreads();
        if (it < KEXT / GBK - 1) {
            #pragma unroll
            for (int q = 0; q < 2; ++q) {
                int idx = tid + q * 256;
                int row = idx >> 2, cs = (idx & 3) * 8;
                *(uint4*)(As + row * ASTR + cs) = pa[q];
                *(uint4*)(Bs + row * ASTR + cs) = pb[q];
            }
            __syncthreads();
        }
    }

    #pragma unroll
    for (int t = 0; t < 2; ++t) {
        int r0 = bi + wm * 32 + t * 16 + (lane >> 2);
        #pragma unroll
        for (int n = 0; n < 8; ++n) {
            int col = bj + wn * 64 + n * 8 + (lane & 3) * 2;
            *(unsigned*)&gC[(size_t)r0 * NPT + col] =
                pack2(qz(acc[t][n][0]), qz(acc[t][n][1]));
            *(unsigned*)&gC[(size_t)(r0 + 8) * NPT + col] =
                pack2(qz(acc[t][n][2]), qz(acc[t][n][3]));
        }
    }
}

#define ROWS_PER_CTA 8
#define IB_ROWS 64

// ---------------- SAFE row logsumexp (records row max) ----------------
__global__ __launch_bounds__(256) void row_lse_safe(int mode) {
    __shared__ float w2[NPT];
    float* __restrict__ out = mode ? gS : gU;

    int tid = threadIdx.x;
    const float4* w4 = (const float4*)gV;
    for (int idx = tid; idx < NPT / 4; idx += 256) {
        float4 t = w4[idx];
        t.x *= LOG2E; t.y *= LOG2E; t.z *= LOG2E; t.w *= LOG2E;
        ((float4*)w2)[idx] = t;
    }
    __syncthreads();

    int warp = tid >> 5, lane = tid & 31;
    int i = blockIdx.x * ROWS_PER_CTA + warp;
    const uint4* __restrict__ rowp = (const uint4*)(gC + (size_t)i * NPT);

    float m0 = NEG_INF, s0 = 0.0f, m1 = NEG_INF, s1 = 0.0f;
    float m2 = NEG_INF, s2 = 0.0f, m3 = NEG_INF, s3 = 0.0f;

    #pragma unroll 4
    for (int c = 0; c < 32; ++c) {
        int idx = c * 32 + lane;
        uint4 rw = __ldcs(rowp + idx);
        const float4* wv = (const float4*)(w2 + (size_t)idx * 8);
        float4 wa = wv[0], wb = wv[1];
        float f0, f1;
        UNPK2(rw.x, f0, f1);
        BUPD(m0, s0, fmaf(f0, KS, wa.x)); BUPD(m1, s1, fmaf(f1, KS, wa.y));
        UNPK2(rw.y, f0, f1);
        BUPD(m2, s2, fmaf(f0, KS, wa.z)); BUPD(m3, s3, fmaf(f1, KS, wa.w));
        UNPK2(rw.z, f0, f1);
        BUPD(m0, s0, fmaf(f0, KS, wb.x)); BUPD(m1, s1, fmaf(f1, KS, wb.y));
        UNPK2(rw.w, f0, f1);
        BUPD(m2, s2, fmaf(f0, KS, wb.z)); BUPD(m3, s3, fmaf(f1, KS, wb.w));
    }

    float ma = fmaxf(m0, m1);
    float sa = s0 * ex2(m0 - ma) + s1 * ex2(m1 - ma);
    float mb = fmaxf(m2, m3);
    float sb = s2 * ex2(m2 - mb) + s3 * ex2(m3 - mb);
    float m = fmaxf(ma, mb);
    float s = sa * ex2(ma - m) + sb * ex2(mb - m);
    #pragma unroll
    for (int off = 16; off; off >>= 1) {
        float mo = __shfl_xor_sync(0xffffffffu, m, off);
        float so = __shfl_xor_sync(0xffffffffu, s, off);
        float mn = fmaxf(m, mo);
        s = s * ex2(m - mn) + so * ex2(mo - mn);
        m = mn;
    }
    if (lane == 0) { out[i] = LOGN - LN2 * (m + log2f(s)); gMU[i] = m; }
}

// ---------------- FAST row logsumexp (frozen per-row shift, f32x2 math) ----------------
__global__ __launch_bounds__(256) void row_lse_fast(int mode) {
    __shared__ float w2[NPT];
    float* __restrict__ out = mode ? gS : gU;

    int tid = threadIdx.x;
    const float4* w4 = (const float4*)gV;
    for (int idx = tid; idx < NPT / 4; idx += 256) {
        float4 t = w4[idx];
        t.x = fmaf(t.x, LOG2E, -W2OFF); t.y = fmaf(t.y, LOG2E, -W2OFF);
        t.z = fmaf(t.z, LOG2E, -W2OFF); t.w = fmaf(t.w, LOG2E, -W2OFF);
        ((float4*)w2)[idx] = t;
    }
    __syncthreads();

    int warp = tid >> 5, lane = tid & 31;
    int i = blockIdx.x * ROWS_PER_CTA + warp;
    float Z0 = gMU[i];
    ull nZ2 = pkf2(-Z0, -Z0);
    ull KS2 = pkf2(KS, KS);
    const uint4* __restrict__ rowp = (const uint4*)(gC + (size_t)i * NPT);

    float s0 = 0.0f, s1 = 0.0f, s2 = 0.0f, s3 = 0.0f;

    #pragma unroll 4
    for (int c = 0; c < 32; ++c) {
        int idx = c * 32 + lane;
        uint4 rw = __ldcs(rowp + idx);
        const float4* wv = (const float4*)(w2 + (size_t)idx * 8);
        float4 wa = wv[0], wb = wv[1];
        ull q2; float z0, z1;
        UNPKP(rw.x, q2);
        upkf2(add2(fma2(q2, KS2, pkf2(wa.x, wa.y)), nZ2), z0, z1);
        s0 += ex2(z0); s1 += ex2(z1);
        UNPKP(rw.y, q2);
        upkf2(add2(fma2(q2, KS2, pkf2(wa.z, wa.w)), nZ2), z0, z1);
        s2 += ex2(z0); s3 += ex2(z1);
        UNPKP(rw.z, q2);
        upkf2(add2(fma2(q2, KS2, pkf2(wb.x, wb.y)), nZ2), z0, z1);
        s0 += ex2(z0); s1 += ex2(z1);
        UNPKP(rw.w, q2);
        upkf2(add2(fma2(q2, KS2, pkf2(wb.z, wb.w)), nZ2), z0, z1);
        s2 += ex2(z0); s3 += ex2(z1);
    }

    float s = (s0 + s1) + (s2 + s3);
    #pragma unroll
    for (int off = 16; off; off >>= 1)
        s += __shfl_xor_sync(0xffffffffu, s, off);
    if (lane == 0) out[i] = LOGN - LN2 * (Z0 + log2f(s));
}

// ---------------- SAFE column logsumexp + combine ----------------
__global__ __launch_bounds__(256) void col_lse_safe() {
    __shared__ float su[IB_ROWS];
    int tid = threadIdx.x;
    int jb = blockIdx.x, ib = blockIdx.y;
    int i0 = ib * IB_ROWS;

    if (tid < IB_ROWS) su[tid] = gU[i0 + tid] * LOG2E;
    __syncthreads();

    int j0 = jb * 2048 + tid * 8;
    const uint4* __restrict__ Cp = (const uint4*)(gC + (size_t)i0 * NPT + j0);

    float m[8], s[8];
    #pragma unroll
    for (int k = 0; k < 8; ++k) { m[k] = NEG_INF; s[k] = 0.0f; }

    #pragma unroll 4
    for (int ii = 0; ii < IB_ROWS; ++ii) {
        uint4 rw = __ldcs(Cp + (size_t)ii * (NPT / 8));
        float u = su[ii];
        float f0, f1;
        UNPK2(rw.x, f0, f1);
        BUPD(m[0], s[0], fmaf(f0, KS, u)); BUPD(m[1], s[1], fmaf(f1, KS, u));
        UNPK2(rw.y, f0, f1);
        BUPD(m[2], s[2], fmaf(f0, KS, u)); BUPD(m[3], s[3], fmaf(f1, KS, u));
        UNPK2(rw.z, f0, f1);
        BUPD(m[4], s[4], fmaf(f0, KS, u)); BUPD(m[5], s[5], fmaf(f1, KS, u));
        UNPK2(rw.w, f0, f1);
        BUPD(m[6], s[6], fmaf(f0, KS, u)); BUPD(m[7], s[7], fmaf(f1, KS, u));
    }

    float* pm = &gPM[(size_t)ib * NPT + j0];
    float* ps = &gPS[(size_t)ib * NPT + j0];
    #pragma unroll
    for (int k = 0; k < 2; ++k) {
        *(float4*)&pm[k * 4] = make_float4(m[k*4+0], m[k*4+1], m[k*4+2], m[k*4+3]);
        *(float4*)&ps[k * 4] = make_float4(s[k*4+0], s[k*4+1], s[k*4+2], s[k*4+3]);
    }
}

__global__ __launch_bounds__(256) void col_combine_safe() {
    int j = blockIdx.x * 256 + threadIdx.x;
    float m = NEG_INF, s = 0.0f;
    #pragma unroll 8
    for (int p = 0; p < 128; ++p) {
        float mp = gPM[(size_t)p * NPT + j];
        float sp = gPS[(size_t)p * NPT + j];
        float mn = fmaxf(m, mp);
        s = s * ex2(m - mn) + sp * ex2(mp - mn);
        m = mn;
    }
    gV[j] = LOGN - LN2 * (m + log2f(s));
    gMV[j] = m;
}

// ---------------- FAST column logsumexp + combine (frozen per-col shift, f32x2) ----------------
__global__ __launch_bounds__(256) void col_lse_fast() {
    __shared__ float su[IB_ROWS];
    int tid = threadIdx.x;
    int jb = blockIdx.x, ib = blockIdx.y;
    int i0 = ib * IB_ROWS;

    if (tid < IB_ROWS) su[tid] = fmaf(gU[i0 + tid], LOG2E, -W2OFF);
    __syncthreads();

    int j0 = jb * 2048 + tid * 8;
    const uint4* __restrict__ Cp = (const uint4*)(gC + (size_t)i0 * NPT + j0);

    ull nZ2[4];
    {
        float4 za = *(const float4*)&gMV[j0];
        float4 zb = *(const float4*)&gMV[j0 + 4];
        nZ2[0] = pkf2(-za.x, -za.y); nZ2[1] = pkf2(-za.z, -za.w);
        nZ2[2] = pkf2(-zb.x, -zb.y); nZ2[3] = pkf2(-zb.z, -zb.w);
    }
    ull KS2 = pkf2(KS, KS);

    float s[8];
    #pragma unroll
    for (int k = 0; k < 8; ++k) s[k] = 0.0f;

    #pragma unroll 4
    for (int ii = 0; ii < IB_ROWS; ++ii) {
        uint4 rw = __ldcs(Cp + (size_t)ii * (NPT / 8));
        float u = su[ii];
        ull u2 = pkf2(u, u);
        ull q2; float z0, z1;
        UNPKP(rw.x, q2);
        upkf2(add2(fma2(q2, KS2, u2), nZ2[0]), z0, z1);
        s[0] += ex2(z0); s[1] += ex2(z1);
        UNPKP(rw.y, q2);
        upkf2(add2(fma2(q2, KS2, u2), nZ2[1]), z0, z1);
        s[2] += ex2(z0); s[3] += ex2(z1);
        UNPKP(rw.z, q2);
        upkf2(add2(fma2(q2, KS2, u2), nZ2[2]), z0, z1);
        s[4] += ex2(z0); s[5] += ex2(z1);
        UNPKP(rw.w, q2);
        upkf2(add2(fma2(q2, KS2, u2), nZ2[3]), z0, z1);
        s[6] += ex2(z0); s[7] += ex2(z1);
    }

    float* ps = &gPS[(size_t)ib * NPT + j0];
    #pragma unroll
    for (int k = 0; k < 2; ++k)
        *(float4*)&ps[k * 4] = make_float4(s[k*4+0], s[k*4+1], s[k*4+2], s[k*4+3]);
}

__global__ __launch_bounds__(256) void col_combine_fast() {
    int j = blockIdx.x * 256 + threadIdx.x;
    float s = 0.0f;
    #pragma unroll 8
    for (int p = 0; p < 128; ++p)
        s += gPS[(size_t)p * NPT + j];
    gV[j] = LOGN - LN2 * (gMV[j] + log2f(s));
}

// ---------------- final value reduction ----------------
__global__ __launch_bounds__(256) void final_kernel(float* __restrict__ out) {
    __shared__ float red[256];
    int tid = threadIdx.x;
    float acc = 0.0f;
    for (int i = tid; i < NPT; i += 256) {
        float fi = gA[i] + gU[i];
        float ri = expf(gU[i] - LOGN - gS[i]);
        float gj = gB[i] + gV[i];
        acc += fi * ri + gj * (1.0f / NPT);
    }
    red[tid] = acc;
    __syncthreads();
    #pragma unroll
    for (int st = 128; st; st >>= 1) {
        if (tid < st) red[tid] += red[tid + st];
        __syncthreads();
    }
    if (tid == 0) out[0] = sqrtf(red[0]);
}

// ---------------- launch ----------------
extern "C" void kernel_launch(void* const* d_in, const int* in_sizes, int n_in,
                              void* d_out, int out_size) {
    const float* X = (const float*)d_in[0];   // source [8192, 256]
    const float* Y = (const float*)d_in[1];   // target [8192, 256]
    float* out = (float*)d_out;

    convert_kernel<<<NPT, 256>>>(X, Y);                  // launch 1 (also norms)
    dim3 gg(NPT / 128, NPT / 128);
    gemm_mma_kernel<<<gg, 256>>>();                      // launch 2
    init_kernel<<<NPT / 256, 256>>>();                   // launch 3

    dim3 cg(4, 128);
    for (int it = 0; it < N_SAFE; ++it) {
        row_lse_safe<<<NPT / ROWS_PER_CTA, 256>>>(0);    // launch 4 = profiled
        col_lse_safe<<<cg, 256>>>();
        col_combine_safe<<<NPT / 256, 256>>>();
    }
    for (int it = N_SAFE; it < 50; ++it) {
        row_lse_fast<<<NPT / ROWS_PER_CTA, 256>>>(0);
        col_lse_fast<<<cg, 256>>>();
        col_combine_fast<<<NPT / 256, 256>>>();
    }
    row_lse_fast<<<NPT / ROWS_PER_CTA, 256>>>(1);        // S_i with final v
    final_kernel<<<1, 256>>>(out);
}